// round 9
// baseline (speedup 1.0000x reference)
#include <cuda_runtime.h>
#include <math.h>
#include <stdint.h>

#define T_    64
#define B_    512
#define NTOK  512
#define NINP  600
#define NHID  600
#define NB    6
#define TOPK_ 4
#define BS_   100
#define ATT   340
#define DK    64
#define DC    32

#define TB    (T_ * B_)              // 32768
#define DEC_OFF   (TB * NTOK)        // 16777216

typedef unsigned long long ull;

// ---------------- f32x2 packed helpers ----------------
__device__ __forceinline__ ull dup2(float x) {
    ull r; asm("mov.b64 %0, {%1, %1};" : "=l"(r) : "f"(x)); return r;
}
__device__ __forceinline__ void fma2(ull &d, ull a, ull b) {
    asm("fma.rn.f32x2 %0, %1, %2, %0;" : "+l"(d) : "l"(a), "l"(b));
}
__device__ __forceinline__ float lo2(ull v) {
    float x, y; asm("mov.b64 {%0, %1}, %2;" : "=f"(x), "=f"(y) : "l"(v)); return x;
}
__device__ __forceinline__ float hi2(ull v) {
    float x, y; asm("mov.b64 {%0, %1}, %2;" : "=f"(x), "=f"(y) : "l"(v)); return y;
}

// ---------------- scratch (device globals) ----------------
__device__ float g_T1[513 * 404];
__device__ float g_W12[513 * 400];
__device__ float g_wqkvx[(size_t)TB * 400];
__device__ float g_out[(size_t)TB * NHID];
__device__ float g_WhT[300 * 100];          // WhT[c][k], contiguous k
__device__ float g_WqkvT[164 * 100];        // [Wq2|Wk2|Wv2]^T, contiguous k

// ---------------- fold kernels ----------------
__global__ void fold1(const float* __restrict__ enc_W, const float* __restrict__ enc_b,
                      const float* __restrict__ Wk,    const float* __restrict__ Wv) {
    int idx = blockIdx.x * blockDim.x + threadIdx.x;
    if (idx >= 513 * 404) return;
    int r = idx / 404, c = idx % 404;
    const float* arow = (r < 512) ? (enc_W + (size_t)r * NINP) : enc_b;
    float acc = 0.f;
    if (c < 64) {
        #pragma unroll 4
        for (int k = 0; k < NINP; k++) acc += arow[k] * __ldg(&Wk[k * DK + c]);
    } else {
        int cc = c - 64;
        #pragma unroll 4
        for (int k = 0; k < NINP; k++) acc += arow[k] * __ldg(&Wv[k * ATT + cc]);
    }
    g_T1[idx] = acc;
}

__global__ void fold2(const float* __restrict__ Wq, const float* __restrict__ Wx) {
    int idx = blockIdx.x * blockDim.x + threadIdx.x;
    if (idx >= 513 * 400) return;
    int r = idx / 400, c = idx % 400;
    float acc = 0.f;
    if (c < 100) {
        const float* t1 = g_T1 + r * 404;
        const float* wq = Wq + c * DK;
        #pragma unroll 8
        for (int k = 0; k < DK; k++) acc += t1[k] * wq[k];
    } else {
        const float* t1 = g_T1 + r * 404 + 64;
        int cc = c - 100;
        #pragma unroll 4
        for (int k = 0; k < ATT; k++) acc += t1[k] * __ldg(&Wx[k * 300 + cc]);
    }
    g_W12[idx] = acc;
}

__global__ void transposeW(const float* __restrict__ Wh,
                           const float* __restrict__ Wq2,
                           const float* __restrict__ Wk2,
                           const float* __restrict__ Wv2) {
    int i = blockIdx.x * blockDim.x + threadIdx.x;
    if (i < 300 * 100) {
        int c = i / 100, k = i % 100;
        g_WhT[i] = Wh[k * 300 + c];
    } else if (i < 300 * 100 + 164 * 100) {
        int j = i - 300 * 100;
        int c = j / 100, k = j % 100;
        float v;
        if (c < 32)      v = Wq2[k * 32 + c];
        else if (c < 64) v = Wk2[k * 32 + (c - 32)];
        else             v = Wv2[k * 100 + (c - 64)];
        g_WqkvT[j] = v;
    }
}

// ---------------- fp32 SGEMM (f32x2): C = A@B + bias (proven R4 version) ----
__device__ __forceinline__ void sgemm_body(
    const float* __restrict__ A, const float* __restrict__ B,
    const float* __restrict__ bias, float* __restrict__ C,
    int M, int N, int K)
{
    __shared__ __align__(16) float As[8][128];
    __shared__ __align__(16) float Bs[8][128];
    const int tid = threadIdx.x;
    const int m0 = blockIdx.y * 128;
    const int n0 = blockIdx.x * 128;
    const int arow = tid >> 1, acol = (tid & 1) * 4;
    const int brow = tid >> 5, bcol = (tid & 31) * 4;
    const int tm = (tid >> 4) * 8, tn = (tid & 15) * 8;

    ull acc2[8][4];
    #pragma unroll
    for (int i = 0; i < 8; i++)
        #pragma unroll
        for (int j = 0; j < 4; j++) acc2[i][j] = 0ull;

    for (int k0 = 0; k0 < K; k0 += 8) {
        float4 av = *(const float4*)(A + (size_t)(m0 + arow) * K + k0 + acol);
        As[acol + 0][arow] = av.x;
        As[acol + 1][arow] = av.y;
        As[acol + 2][arow] = av.z;
        As[acol + 3][arow] = av.w;
        float4 bv = make_float4(0.f, 0.f, 0.f, 0.f);
        if (n0 + bcol < N)
            bv = *(const float4*)(B + (size_t)(k0 + brow) * N + n0 + bcol);
        *(float4*)&Bs[brow][bcol] = bv;
        __syncthreads();
        #pragma unroll
        for (int k = 0; k < 8; k++) {
            float4 a0 = *(const float4*)&As[k][tm];
            float4 a1 = *(const float4*)&As[k][tm + 4];
            ulonglong2 b01 = *(const ulonglong2*)&Bs[k][tn];
            ulonglong2 b23 = *(const ulonglong2*)&Bs[k][tn + 4];
            ull ad[8];
            ad[0] = dup2(a0.x); ad[1] = dup2(a0.y); ad[2] = dup2(a0.z); ad[3] = dup2(a0.w);
            ad[4] = dup2(a1.x); ad[5] = dup2(a1.y); ad[6] = dup2(a1.z); ad[7] = dup2(a1.w);
            #pragma unroll
            for (int i = 0; i < 8; i++) {
                fma2(acc2[i][0], ad[i], b01.x);
                fma2(acc2[i][1], ad[i], b01.y);
                fma2(acc2[i][2], ad[i], b23.x);
                fma2(acc2[i][3], ad[i], b23.y);
            }
        }
        __syncthreads();
    }
    #pragma unroll
    for (int i = 0; i < 8; i++) {
        int m = m0 + tm + i;
        #pragma unroll
        for (int j2 = 0; j2 < 4; j2++) {
            int n = n0 + tn + j2 * 2;
            if (n < N) {
                float2 v;
                v.x = lo2(acc2[i][j2]) + bias[n + 0];
                v.y = hi2(acc2[i][j2]) + bias[n + 1];
                *(float2*)(C + (size_t)m * N + n) = v;
            }
        }
    }
}

__global__ __launch_bounds__(256) void gemm_wqkvx(const float* __restrict__ input) {
    sgemm_body(input, g_W12, g_W12 + 512 * 400, g_wqkvx, TB, 400, NTOK);
}

__global__ __launch_bounds__(256) void gemm_dec(const float* __restrict__ dec_W,
                                                const float* __restrict__ dec_b,
                                                float* __restrict__ C) {
    sgemm_body(g_out, dec_W, dec_b, C, TB, NTOK, NHID);
}

// ---------------- persistent steps: 4 independent 160-thread batch groups ----
struct __align__(16) GroupSmem {
    float hb[100][8];     // [k][slot], slots 0..5 valid (pitch 8 = 32B rows)
    float hn[100][8];
    float hg[6][304];     // [slot][col], 300 valid
    float vx[304];        // 300 valid
    float q2[6][36];
    float k2[6][36];
    float v2[6][104];
    float p2[6][8];
    float sarr[8], parr[8], bm[8];
};

#define GBAR() asm volatile("bar.sync %0, %1;" :: "r"(grp + 1), "r"(160) : "memory")

__global__ __launch_bounds__(640, 1) void steps_persistent(
    const float* __restrict__ hidden,
    const float* __restrict__ masks,
    const float* __restrict__ gru_b,
    float* __restrict__ hT_out,
    float* __restrict__ bmask_out)
{
    extern __shared__ __align__(16) char smem_raw[];
    GroupSmem* G = reinterpret_cast<GroupSmem*>(smem_raw);

    const int tid = threadIdx.x;
    const int grp = tid / 160;          // 0..3, warp-aligned (160 = 5 warps)
    const int gt  = tid % 160;
    GroupSmem& g = G[grp];
    const int b = blockIdx.x * 4 + grp;

    // initial state: hidden[b][n*100+j] -> hb[j][n]
    for (int i = gt; i < 600; i += 160)
        g.hb[i % 100][i / 100] = hidden[b * NHID + i];
    __syncthreads();

    for (int t = 0; t < T_; t++) {
        const float m = masks[t * B_ + b];

        // ---- I1: vx prefetch (regs) | hg = hb@Wh GEMV | scores + topk
        float4 vxr;
        if (gt < 75)
            vxr = *(const float4*)(g_wqkvx + (size_t)(t * B_ + b) * 400 + 100 + gt * 4);

        if (gt < 150) {
            const int c0 = gt, c1 = gt + 150;
            ull a0[3] = {0, 0, 0}, a1[3] = {0, 0, 0};
            const float* w0 = g_WhT + c0 * 100;
            const float* w1 = g_WhT + c1 * 100;
            for (int k = 0; k < 100; k += 4) {
                float4 wv0 = *(const float4*)(w0 + k);
                float4 wv1 = *(const float4*)(w1 + k);
                #pragma unroll
                for (int kk = 0; kk < 4; kk++) {
                    const float* hrow = &g.hb[k + kk][0];
                    ulonglong2 h01 = *(const ulonglong2*)hrow;       // slots 0-3
                    ull h45 = *(const ull*)(hrow + 4);               // slots 4-5
                    float wa = (kk == 0) ? wv0.x : (kk == 1) ? wv0.y : (kk == 2) ? wv0.z : wv0.w;
                    float wb = (kk == 0) ? wv1.x : (kk == 1) ? wv1.y : (kk == 2) ? wv1.z : wv1.w;
                    ull wda = dup2(wa), wdb = dup2(wb);
                    fma2(a0[0], h01.x, wda); fma2(a0[1], h01.y, wda); fma2(a0[2], h45, wda);
                    fma2(a1[0], h01.x, wdb); fma2(a1[1], h01.y, wdb); fma2(a1[2], h45, wdb);
                }
            }
            #pragma unroll
            for (int p = 0; p < 3; p++) {
                g.hg[2 * p][c0]     = lo2(a0[p]);
                g.hg[2 * p + 1][c0] = hi2(a0[p]);
                g.hg[2 * p][c1]     = lo2(a1[p]);
                g.hg[2 * p + 1][c1] = hi2(a1[p]);
            }
        } else if (gt < 156) {
            // scores: s[slot] = m * sc1 * <hb[:,slot], wqk>, p1 = sigmoid(s)
            const int slot = gt - 150;
            const float* wq = g_wqkvx + (size_t)(t * B_ + b) * 400;
            float sc = 0.f;
            for (int k = 0; k < 100; k += 4) {
                float4 wv = __ldg((const float4*)(wq + k));
                sc += g.hb[k][slot] * wv.x + g.hb[k + 1][slot] * wv.y
                    + g.hb[k + 2][slot] * wv.z + g.hb[k + 3][slot] * wv.w;
            }
            sc *= 0.125f * m;
            g.sarr[slot] = sc;
            g.parr[slot] = 1.f / (1.f + expf(-sc));
            __syncwarp(0x0FC00000u);    // lanes 22-27 of this warp (gt 150-155)
            // top-4-of-6 (jax tie-break: lower index wins)
            float sn = g.sarr[slot];
            int cnt = 0;
            #pragma unroll
            for (int m2 = 0; m2 < 6; m2++) {
                float sm = g.sarr[m2];
                if (sm > sn || (sm == sn && m2 < slot)) cnt++;
            }
            float v = (cnt < TOPK_) ? 1.f : 0.f;
            g.bm[slot] = v;
            bmask_out[(size_t)t * B_ * NB + b * NB + slot] = v;
        }
        if (gt < 75) *(float4*)&g.vx[gt * 4] = vxr;
        GBAR();   // hg, parr, bm, vx ready

        // ---- P2: GRU gates -> hn  (mask applied here)
        for (int i = gt; i < 600; i += 160) {
            int slot = i / 100, j = i % 100;
            float p = g.parr[slot];
            float xr = p * g.vx[j]       + __ldg(&gru_b[j]);
            float xz = p * g.vx[j + 100] + __ldg(&gru_b[j + 100]);
            float xn = p * g.vx[j + 200] + __ldg(&gru_b[j + 200]);
            float r_ = 1.f / (1.f + expf(-(xr + m * g.hg[slot][j])));
            float z_ = 1.f / (1.f + expf(-(xz + m * g.hg[slot][j + 100])));
            float nn = tanhf(xn + r_ * (m * g.hg[slot][j + 200]));
            g.hn[j][slot] = (1.f - z_) * nn + z_ * (m * g.hb[j][slot]);
        }
        GBAR();   // hn ready

        // ---- P3: q2/k2/v2 = hn @ [Wq2|Wk2|Wv2]  (164 cols)
        #pragma unroll
        for (int rep = 0; rep < 2; rep++) {
            int col = (rep == 0) ? gt : 160 + gt;
            if (rep == 1 && gt >= 4) break;
            ull acc[3] = {0, 0, 0};
            const float* wt = g_WqkvT + col * 100;
            for (int k = 0; k < 100; k += 4) {
                float4 wv = *(const float4*)(wt + k);
                #pragma unroll
                for (int kk = 0; kk < 4; kk++) {
                    const float* hrow = &g.hn[k + kk][0];
                    ulonglong2 h01 = *(const ulonglong2*)hrow;
                    ull h45 = *(const ull*)(hrow + 4);
                    float w = (kk == 0) ? wv.x : (kk == 1) ? wv.y : (kk == 2) ? wv.z : wv.w;
                    ull wd = dup2(w);
                    fma2(acc[0], h01.x, wd); fma2(acc[1], h01.y, wd); fma2(acc[2], h45, wd);
                }
            }
            #pragma unroll
            for (int p = 0; p < 3; p++) {
                float x = lo2(acc[p]), y = hi2(acc[p]);
                int s0 = 2 * p, s1 = 2 * p + 1;
                if (col < 32)      { g.q2[s0][col] = x;      g.q2[s1][col] = y; }
                else if (col < 64) { g.k2[s0][col - 32] = x; g.k2[s1][col - 32] = y; }
                else               { g.v2[s0][col - 64] = x; g.v2[s1][col - 64] = y; }
            }
        }
        GBAR();   // q2/k2/v2 ready

        // ---- P4: attention-2 scores + softmax (warp-local, one group bar)
        if (gt < 48) {
            int n = gt >> 3, m2 = gt & 7;
            if (m2 < 6) {
                const float* qr = g.q2[n];
                const float* kr = g.k2[m2];
                float sc = 0.f;
                #pragma unroll
                for (int d = 0; d < 32; d++) sc += qr[d] * kr[d];
                g.p2[n][m2] = sc * 0.17677669529663687f;    // 1/sqrt(32)
            }
            __syncwarp((gt < 32) ? 0xFFFFFFFFu : 0x0000FFFFu);
            if (m2 == 0) {
                float mx = -1e30f;
                #pragma unroll
                for (int q = 0; q < 6; q++) mx = fmaxf(mx, g.p2[n][q]);
                float e[6], sum = 0.f;
                #pragma unroll
                for (int q = 0; q < 6; q++) { e[q] = expf(g.p2[n][q] - mx); sum += e[q]; }
                float inv = 1.f / sum;
                #pragma unroll
                for (int q = 0; q < 6; q++) g.p2[n][q] = e[q] * inv;
            }
        }
        GBAR();   // p2 ready

        // ---- P5: hc = hn + p2@v2; blend; update state; coalesced history store
        {
            float* dst = g_out + (size_t)(t * B_ + b) * NHID;
            for (int i = gt; i < 600; i += 160) {
                int slot = i / 100, j = i % 100;
                float acc = g.hn[j][slot];
                #pragma unroll
                for (int m2 = 0; m2 < 6; m2++) acc += g.p2[slot][m2] * g.v2[m2][j];
                float res = (g.bm[slot] > 0.5f) ? acc : (m * g.hb[j][slot]);
                g.hb[j][slot] = res;
                dst[i] = res;                // consecutive gt -> consecutive addr
            }
        }
        GBAR();   // end of step: hb final before next I1
    }

    __syncthreads();
    for (int i = gt; i < 600; i += 160)
        hT_out[b * NHID + i] = g.hb[i % 100][i / 100];
}

// ---------------- launch ----------------
extern "C" void kernel_launch(void* const* d_in, const int* in_sizes, int n_in,
                              void* d_out, int out_size) {
    const float* input  = (const float*)d_in[0];
    const float* hidden = (const float*)d_in[1];
    const float* masks  = (const float*)d_in[2];
    const float* enc_W  = (const float*)d_in[3];
    const float* enc_b  = (const float*)d_in[4];
    const float* Wq     = (const float*)d_in[5];
    const float* Wk     = (const float*)d_in[6];
    const float* Wv     = (const float*)d_in[7];
    const float* Wx     = (const float*)d_in[8];
    const float* Wh     = (const float*)d_in[9];
    const float* gru_b  = (const float*)d_in[10];
    const float* Wq2    = (const float*)d_in[11];
    const float* Wk2    = (const float*)d_in[12];
    const float* Wv2    = (const float*)d_in[13];
    const float* dec_W  = (const float*)d_in[14];
    const float* dec_b  = (const float*)d_in[15];
    float* out = (float*)d_out;

    static int attr_set = 0;
    int step_smem = (int)(4 * sizeof(GroupSmem));
    if (!attr_set) {
        cudaFuncSetAttribute(steps_persistent,
                             cudaFuncAttributeMaxDynamicSharedMemorySize, step_smem);
        attr_set = 1;
    }

    fold1<<<(513 * 404 + 255) / 256, 256>>>(enc_W, enc_b, Wk, Wv);
    fold2<<<(513 * 400 + 255) / 256, 256>>>(Wq, Wx);
    transposeW<<<(300 * 100 + 164 * 100 + 255) / 256, 256>>>(Wh, Wq2, Wk2, Wv2);

    gemm_wqkvx<<<dim3(4, TB / 128), 256>>>(input);

    float* hT_out    = out + DEC_OFF;
    float* bmask_out = out + DEC_OFF + B_ * NHID;
    steps_persistent<<<B_ / 4, 640, step_smem>>>(hidden, masks, gru_b, hT_out, bmask_out);

    gemm_dec<<<dim3(4, TB / 128), 256>>>(dec_W, dec_b, out);
}

// round 10
// speedup vs baseline: 1.1607x; 1.1607x over previous
#include <cuda_runtime.h>
#include <math.h>
#include <stdint.h>

#define T_    64
#define B_    512
#define NTOK  512
#define NINP  600
#define NHID  600
#define NB    6
#define TOPK_ 4
#define BS_   100
#define ATT   340
#define DK    64
#define DC    32

#define TB    (T_ * B_)              // 32768
#define DEC_OFF   (TB * NTOK)        // 16777216
#define OSTRIDE   608                // g_out row stride (16-multiple, 600 valid)

typedef unsigned long long ull;

// ---------------- f32x2 packed helpers ----------------
__device__ __forceinline__ ull dup2(float x) {
    ull r; asm("mov.b64 %0, {%1, %1};" : "=l"(r) : "f"(x)); return r;
}
__device__ __forceinline__ void fma2(ull &d, ull a, ull b) {
    asm("fma.rn.f32x2 %0, %1, %2, %0;" : "+l"(d) : "l"(a), "l"(b));
}
__device__ __forceinline__ float lo2(ull v) {
    float x, y; asm("mov.b64 {%0, %1}, %2;" : "=f"(x), "=f"(y) : "l"(v)); return x;
}
__device__ __forceinline__ float hi2(ull v) {
    float x, y; asm("mov.b64 {%0, %1}, %2;" : "=f"(x), "=f"(y) : "l"(v)); return y;
}

// ---------------- scratch (device globals) ----------------
__device__ float g_T1[513 * 404];
__device__ float g_W12[513 * 400];
__device__ float g_wqkvx[(size_t)TB * 400];
__device__ float g_out[(size_t)TB * OSTRIDE];
__device__ float g_WhT[300 * 100];          // WhT[c][k] contiguous k
__device__ float g_WqkvT[164 * 100];        // [Wq2|Wk2|Wv2]^T, contiguous k

// ---------------- fold kernels ----------------
__global__ void fold1(const float* __restrict__ enc_W, const float* __restrict__ enc_b,
                      const float* __restrict__ Wk,    const float* __restrict__ Wv) {
    int idx = blockIdx.x * blockDim.x + threadIdx.x;
    if (idx >= 513 * 404) return;
    int r = idx / 404, c = idx % 404;
    const float* arow = (r < 512) ? (enc_W + (size_t)r * NINP) : enc_b;
    float acc = 0.f;
    if (c < 64) {
        #pragma unroll 4
        for (int k = 0; k < NINP; k++) acc += arow[k] * __ldg(&Wk[k * DK + c]);
    } else {
        int cc = c - 64;
        #pragma unroll 4
        for (int k = 0; k < NINP; k++) acc += arow[k] * __ldg(&Wv[k * ATT + cc]);
    }
    g_T1[idx] = acc;
}

__global__ void fold2(const float* __restrict__ Wq, const float* __restrict__ Wx) {
    int idx = blockIdx.x * blockDim.x + threadIdx.x;
    if (idx >= 513 * 400) return;
    int r = idx / 400, c = idx % 400;
    float acc = 0.f;
    if (c < 100) {
        const float* t1 = g_T1 + r * 404;
        const float* wq = Wq + c * DK;
        #pragma unroll 8
        for (int k = 0; k < DK; k++) acc += t1[k] * wq[k];
    } else {
        const float* t1 = g_T1 + r * 404 + 64;
        int cc = c - 100;
        #pragma unroll 4
        for (int k = 0; k < ATT; k++) acc += t1[k] * __ldg(&Wx[k * 300 + cc]);
    }
    g_W12[idx] = acc;
}

__global__ void transposeW(const float* __restrict__ Wh,
                           const float* __restrict__ Wq2,
                           const float* __restrict__ Wk2,
                           const float* __restrict__ Wv2) {
    int i = blockIdx.x * blockDim.x + threadIdx.x;
    if (i < 300 * 100) {
        int c = i / 100, k = i % 100;
        g_WhT[i] = Wh[k * 300 + c];
    } else if (i < 300 * 100 + 164 * 100) {
        int j = i - 300 * 100;
        int c = j / 100, k = j % 100;
        float v;
        if (c < 32)      v = Wq2[k * 32 + c];
        else if (c < 64) v = Wk2[k * 32 + (c - 32)];
        else             v = Wv2[k * 100 + (c - 64)];
        g_WqkvT[j] = v;
    }
}

// ---------------- fp32 SGEMM, BK=16 double-buffered: C = A@B + bias ----------
// A: M x Astride (row-major). B: Kt x N (row-major); rows >= Kvalid read as 0.
__device__ __forceinline__ void sgemm_body(
    const float* __restrict__ A, const float* __restrict__ B,
    const float* __restrict__ bias, float* __restrict__ C,
    int M, int N, int Kt, int Kvalid, int Astride)
{
    __shared__ __align__(16) float As[2][16][128];
    __shared__ __align__(16) float Bs[2][16][128];
    const int tid = threadIdx.x;
    const int m0 = blockIdx.y * 128;
    const int n0 = blockIdx.x * 128;
    const int arow = tid >> 1, ac0 = (tid & 1) * 8;    // A loader: row, k-offset
    const int brow = tid >> 4, bc0 = (tid & 15) * 8;   // B loader: k-row, n-offset
    const int tm = (tid >> 4) * 8, tn = (tid & 15) * 8;
    const int Kc = Kt / 16;

    ull acc2[8][4];
    #pragma unroll
    for (int i = 0; i < 8; i++)
        #pragma unroll
        for (int j = 0; j < 4; j++) acc2[i][j] = 0ull;

    // helper lambdas (inlined by compiler)
    // ---- load chunk 0 directly into buffer 0
    {
        const float* ga = A + (size_t)(m0 + arow) * Astride + ac0;
        #pragma unroll
        for (int h = 0; h < 2; h++) {
            float4 av = *(const float4*)(ga + h * 4);
            As[0][ac0 + h * 4 + 0][arow] = av.x;
            As[0][ac0 + h * 4 + 1][arow] = av.y;
            As[0][ac0 + h * 4 + 2][arow] = av.z;
            As[0][ac0 + h * 4 + 3][arow] = av.w;
        }
        #pragma unroll
        for (int h = 0; h < 2; h++) {
            float4 bv = make_float4(0.f, 0.f, 0.f, 0.f);
            if (brow < Kvalid && n0 + bc0 + h * 4 < N)
                bv = *(const float4*)(B + (size_t)brow * N + n0 + bc0 + h * 4);
            *(float4*)&Bs[0][brow][bc0 + h * 4] = bv;
        }
    }
    __syncthreads();

    for (int kc = 0; kc < Kc; kc++) {
        float4 pa[2], pb[2];
        const bool more = (kc + 1 < Kc);
        if (more) {
            const int k1 = (kc + 1) * 16;
            const float* ga = A + (size_t)(m0 + arow) * Astride + k1 + ac0;
            #pragma unroll
            for (int h = 0; h < 2; h++) pa[h] = *(const float4*)(ga + h * 4);
            #pragma unroll
            for (int h = 0; h < 2; h++) {
                pb[h] = make_float4(0.f, 0.f, 0.f, 0.f);
                if (k1 + brow < Kvalid && n0 + bc0 + h * 4 < N)
                    pb[h] = *(const float4*)(B + (size_t)(k1 + brow) * N + n0 + bc0 + h * 4);
            }
        }

        const int cb = kc & 1;
        #pragma unroll
        for (int k = 0; k < 16; k++) {
            float4 a0 = *(const float4*)&As[cb][k][tm];
            float4 a1 = *(const float4*)&As[cb][k][tm + 4];
            ulonglong2 b01 = *(const ulonglong2*)&Bs[cb][k][tn];
            ulonglong2 b23 = *(const ulonglong2*)&Bs[cb][k][tn + 4];
            ull ad[8];
            ad[0] = dup2(a0.x); ad[1] = dup2(a0.y); ad[2] = dup2(a0.z); ad[3] = dup2(a0.w);
            ad[4] = dup2(a1.x); ad[5] = dup2(a1.y); ad[6] = dup2(a1.z); ad[7] = dup2(a1.w);
            #pragma unroll
            for (int i = 0; i < 8; i++) {
                fma2(acc2[i][0], ad[i], b01.x);
                fma2(acc2[i][1], ad[i], b01.y);
                fma2(acc2[i][2], ad[i], b23.x);
                fma2(acc2[i][3], ad[i], b23.y);
            }
        }

        if (more) {
            const int nb = cb ^ 1;
            #pragma unroll
            for (int h = 0; h < 2; h++) {
                As[nb][ac0 + h * 4 + 0][arow] = pa[h].x;
                As[nb][ac0 + h * 4 + 1][arow] = pa[h].y;
                As[nb][ac0 + h * 4 + 2][arow] = pa[h].z;
                As[nb][ac0 + h * 4 + 3][arow] = pa[h].w;
                *(float4*)&Bs[nb][brow][bc0 + h * 4] = pb[h];
            }
            __syncthreads();
        }
    }

    #pragma unroll
    for (int i = 0; i < 8; i++) {
        int m = m0 + tm + i;
        #pragma unroll
        for (int j2 = 0; j2 < 4; j2++) {
            int n = n0 + tn + j2 * 2;
            if (n < N) {
                float2 v;
                v.x = lo2(acc2[i][j2]) + bias[n + 0];
                v.y = hi2(acc2[i][j2]) + bias[n + 1];
                *(float2*)(C + (size_t)m * N + n) = v;
            }
        }
    }
}

__global__ __launch_bounds__(256) void gemm_wqkvx(const float* __restrict__ input) {
    sgemm_body(input, g_W12, g_W12 + 512 * 400, g_wqkvx, TB, 400, 512, 512, 512);
}

__global__ __launch_bounds__(256) void gemm_dec(const float* __restrict__ dec_W,
                                                const float* __restrict__ dec_b,
                                                float* __restrict__ C) {
    sgemm_body(g_out, dec_W, dec_b, C, TB, NTOK, OSTRIDE, NHID, OSTRIDE);
}

// ---------------- persistent steps: 4 batches/block, grid 128, 640 threads ----
// (R4 kernel verbatim; only g_out stride + pad-zero writes changed)
struct StepSmem {
    float hb[100][32];
    float hn[100][32];
    float hg[24][301];
    float wqk[4][100];
    float vx[4][300];
    float sarr[24], parr[24], bm[24];
    float q2[24][33], k2[24][33];
    float v2[24][101];
    float p2[24][8];
};

__global__ __launch_bounds__(640, 1) void steps_persistent(
    const float* __restrict__ hidden,
    const float* __restrict__ masks,
    const float* __restrict__ gru_b,
    float* __restrict__ hT_out,
    float* __restrict__ bmask_out)
{
    extern __shared__ __align__(16) char smem_raw[];
    StepSmem& s = *reinterpret_cast<StepSmem*>(smem_raw);

    const int tid = threadIdx.x;
    const int b0 = blockIdx.x * 4;

    for (int i = tid; i < 2400; i += 640) {
        int bb = i / 600, j = i % 600;
        s.hb[j % 100][bb * 6 + j / 100] = hidden[(b0 + bb) * NHID + j];
    }
    // zero g_out pad columns for all t (once)
    for (int i = tid; i < T_ * 4 * (OSTRIDE - NHID); i += 640) {
        int t = i / (4 * (OSTRIDE - NHID));
        int r = i % (4 * (OSTRIDE - NHID));
        int bb = r / (OSTRIDE - NHID), c = r % (OSTRIDE - NHID);
        g_out[((size_t)t * B_ + b0 + bb) * OSTRIDE + NHID + c] = 0.f;
    }

    for (int t = 0; t < T_; t++) {
        __syncthreads();   // b1

        // ---- interval 1: hg = hb@Wh (raw)  |  warp19: prefetch+scores+topk
        if (tid < 600) {
            const int col = (tid < 300) ? tid : tid - 300;
            const int g   = (tid < 300) ? 0 : 12;
            ull acc[6] = {0, 0, 0, 0, 0, 0};
            const float* wt = g_WhT + col * 100;
            for (int k = 0; k < 100; k += 4) {
                float4 wv = *(const float4*)(wt + k);
                #pragma unroll
                for (int kk = 0; kk < 4; kk++) {
                    float w = (kk == 0) ? wv.x : (kk == 1) ? wv.y : (kk == 2) ? wv.z : wv.w;
                    ull wd = dup2(w);
                    const ulonglong2* hr = (const ulonglong2*)&s.hb[k + kk][g];
                    ulonglong2 h01 = hr[0], h23 = hr[1], h45 = hr[2];
                    fma2(acc[0], h01.x, wd); fma2(acc[1], h01.y, wd);
                    fma2(acc[2], h23.x, wd); fma2(acc[3], h23.y, wd);
                    fma2(acc[4], h45.x, wd); fma2(acc[5], h45.y, wd);
                }
            }
            #pragma unroll
            for (int p = 0; p < 6; p++) {
                s.hg[g + 2 * p][col]     = lo2(acc[p]);
                s.hg[g + 2 * p + 1][col] = hi2(acc[p]);
            }
        } else if (tid >= 608) {
            const int lane = tid - 608;
            const float* src = g_wqkvx + (size_t)(t * B_ + b0) * 400;
            for (int j = lane; j < 100; j += 32) {
                int bb = j / 25, c4 = j % 25;
                *(float4*)&s.wqk[bb][c4 * 4] = *(const float4*)(src + bb * 400 + c4 * 4);
            }
            for (int j = lane; j < 300; j += 32) {
                int bb = j / 75, c4 = j % 75;
                *(float4*)&s.vx[bb][c4 * 4] = *(const float4*)(src + bb * 400 + 100 + c4 * 4);
            }
            __syncwarp();
            if (lane < 24) {
                const int u = lane, bb = u / 6;
                const float m = masks[t * B_ + b0 + bb];
                const float* w = s.wqk[bb];
                float sc = 0.f;
                #pragma unroll 4
                for (int k = 0; k < 100; k++) sc += s.hb[k][u] * w[k];
                sc *= 0.125f * m;
                s.sarr[u] = sc;
                s.parr[u] = 1.f / (1.f + expf(-sc));
            }
            __syncwarp();
            if (lane < 24) {
                const int u = lane, bb = u / 6, n = u % 6;
                float sn = s.sarr[u];
                int cnt = 0;
                #pragma unroll
                for (int m2 = 0; m2 < 6; m2++) {
                    float sm = s.sarr[bb * 6 + m2];
                    if (sm > sn || (sm == sn && m2 < n)) cnt++;
                }
                float v = (cnt < TOPK_) ? 1.f : 0.f;
                s.bm[u] = v;
                bmask_out[(size_t)t * B_ * NB + (b0 + bb) * NB + n] = v;
            }
        }
        __syncthreads();   // b2

        // ---- phase C: GRU gates -> hn
        {
            const int u = tid & 31, jb = tid >> 5;
            if (u < 24) {
                const int bb = u / 6;
                const float m = masks[t * B_ + b0 + bb];
                const float p = s.parr[u];
                for (int j = jb; j < 100; j += 20) {
                    float xr = p * s.vx[bb][j]       + gru_b[j];
                    float xz = p * s.vx[bb][j + 100] + gru_b[j + 100];
                    float xn = p * s.vx[bb][j + 200] + gru_b[j + 200];
                    float r  = 1.f / (1.f + expf(-(xr + m * s.hg[u][j])));
                    float z  = 1.f / (1.f + expf(-(xz + m * s.hg[u][j + 100])));
                    float nn = tanhf(xn + r * (m * s.hg[u][j + 200]));
                    s.hn[j][u] = (1.f - z) * nn + z * (m * s.hb[j][u]);
                }
            }
        }
        __syncthreads();   // b3

        // ---- phase D: q2/k2/v2 = hn @ [Wq2|Wk2|Wv2]
        if (tid < 328) {
            const int col = (tid < 164) ? tid : tid - 164;
            const int g   = (tid < 164) ? 0 : 12;
            ull acc[6] = {0, 0, 0, 0, 0, 0};
            const float* wt = g_WqkvT + col * 100;
            for (int k = 0; k < 100; k += 4) {
                float4 wv = *(const float4*)(wt + k);
                #pragma unroll
                for (int kk = 0; kk < 4; kk++) {
                    float w = (kk == 0) ? wv.x : (kk == 1) ? wv.y : (kk == 2) ? wv.z : wv.w;
                    ull wd = dup2(w);
                    const ulonglong2* hr = (const ulonglong2*)&s.hn[k + kk][g];
                    ulonglong2 h01 = hr[0], h23 = hr[1], h45 = hr[2];
                    fma2(acc[0], h01.x, wd); fma2(acc[1], h01.y, wd);
                    fma2(acc[2], h23.x, wd); fma2(acc[3], h23.y, wd);
                    fma2(acc[4], h45.x, wd); fma2(acc[5], h45.y, wd);
                }
            }
            #pragma unroll
            for (int p = 0; p < 6; p++) {
                float x = lo2(acc[p]), y = hi2(acc[p]);
                int u0 = g + 2 * p, u1 = g + 2 * p + 1;
                if (col < 32)      { s.q2[u0][col] = x;      s.q2[u1][col] = y; }
                else if (col < 64) { s.k2[u0][col - 32] = x; s.k2[u1][col - 32] = y; }
                else               { s.v2[u0][col - 64] = x; s.v2[u1][col - 64] = y; }
            }
        }
        __syncthreads();   // b4

        // ---- phase E: attention-2 scores + softmax
        if (tid < 128) {
            const int wd = tid >> 5, lane = tid & 31;
            const int bb = wd;
            for (int job = lane; job < 36; job += 32) {
                int n = job / 6, m2 = job % 6;
                const float* qr = s.q2[bb * 6 + n];
                const float* kr = s.k2[bb * 6 + m2];
                float sc = 0.f;
                #pragma unroll
                for (int d = 0; d < 32; d++) sc += qr[d] * kr[d];
                s.p2[bb * 6 + n][m2] = sc * 0.17677669529663687f;
            }
            __syncwarp();
            if (lane < 6) {
                const int u = bb * 6 + lane;
                float mx = -1e30f;
                #pragma unroll
                for (int m2 = 0; m2 < 6; m2++) mx = fmaxf(mx, s.p2[u][m2]);
                float e[6], sum = 0.f;
                #pragma unroll
                for (int m2 = 0; m2 < 6; m2++) { e[m2] = expf(s.p2[u][m2] - mx); sum += e[m2]; }
                float inv = 1.f / sum;
                #pragma unroll
                for (int m2 = 0; m2 < 6; m2++) s.p2[u][m2] = e[m2] * inv;
            }
        }
        __syncthreads();   // b5

        // ---- phase F: hc = hn + p2@v2; blend; write state + history
        {
            const int u = tid & 31, jb = tid >> 5;
            if (u < 24) {
                const int bb = u / 6;
                const float m = masks[t * B_ + b0 + bb];
                const float bmu = s.bm[u];
                float pr[6];
                #pragma unroll
                for (int m2 = 0; m2 < 6; m2++) pr[m2] = s.p2[u][m2];
                for (int j = jb; j < 100; j += 20) {
                    float acc = s.hn[j][u];
                    #pragma unroll
                    for (int m2 = 0; m2 < 6; m2++) acc += pr[m2] * s.v2[bb * 6 + m2][j];
                    float res = (bmu > 0.5f) ? acc : (m * s.hb[j][u]);
                    s.hb[j][u] = res;
                    g_out[((size_t)t * B_ + b0 + bb) * OSTRIDE + (u % 6) * 100 + j] = res;
                }
            }
        }
    }

    __syncthreads();
    for (int i = tid; i < 2400; i += 640) {
        int bb = i / 600, j = i % 600;
        hT_out[(b0 + bb) * NHID + j] = s.hb[j % 100][bb * 6 + j / 100];
    }
}

// ---------------- launch ----------------
extern "C" void kernel_launch(void* const* d_in, const int* in_sizes, int n_in,
                              void* d_out, int out_size) {
    const float* input  = (const float*)d_in[0];
    const float* hidden = (const float*)d_in[1];
    const float* masks  = (const float*)d_in[2];
    const float* enc_W  = (const float*)d_in[3];
    const float* enc_b  = (const float*)d_in[4];
    const float* Wq     = (const float*)d_in[5];
    const float* Wk     = (const float*)d_in[6];
    const float* Wv     = (const float*)d_in[7];
    const float* Wx     = (const float*)d_in[8];
    const float* Wh     = (const float*)d_in[9];
    const float* gru_b  = (const float*)d_in[10];
    const float* Wq2    = (const float*)d_in[11];
    const float* Wk2    = (const float*)d_in[12];
    const float* Wv2    = (const float*)d_in[13];
    const float* dec_W  = (const float*)d_in[14];
    const float* dec_b  = (const float*)d_in[15];
    float* out = (float*)d_out;

    static int attr_set = 0;
    int step_smem = (int)sizeof(StepSmem);
    if (!attr_set) {
        cudaFuncSetAttribute(steps_persistent,
                             cudaFuncAttributeMaxDynamicSharedMemorySize, step_smem);
        attr_set = 1;
    }

    fold1<<<(513 * 404 + 255) / 256, 256>>>(enc_W, enc_b, Wk, Wv);
    fold2<<<(513 * 400 + 255) / 256, 256>>>(Wq, Wx);
    transposeW<<<(300 * 100 + 164 * 100 + 255) / 256, 256>>>(Wh, Wq2, Wk2, Wv2);

    gemm_wqkvx<<<dim3(4, TB / 128), 256>>>(input);

    float* hT_out    = out + DEC_OFF;
    float* bmask_out = out + DEC_OFF + B_ * NHID;
    steps_persistent<<<B_ / 4, 640, step_smem>>>(hidden, masks, gru_b, hT_out, bmask_out);

    gemm_dec<<<dim3(4, TB / 128), 256>>>(dec_W, dec_b, out);
}

// round 12
// speedup vs baseline: 1.2394x; 1.0679x over previous
#include <cuda_runtime.h>
#include <math.h>
#include <stdint.h>

#define T_    64
#define B_    512
#define NTOK  512
#define NINP  600
#define NHID  600
#define NB    6
#define TOPK_ 4
#define BS_   100
#define ATT   340
#define DK    64
#define DC    32

#define TB    (T_ * B_)              // 32768
#define DEC_OFF   (TB * NTOK)        // 16777216
#define OSTRIDE   608                // g_out row stride (16-multiple, 600 valid)

typedef unsigned long long ull;

// ---------------- f32x2 packed helpers ----------------
__device__ __forceinline__ ull dup2(float x) {
    ull r; asm("mov.b64 %0, {%1, %1};" : "=l"(r) : "f"(x)); return r;
}
__device__ __forceinline__ void fma2(ull &d, ull a, ull b) {
    asm("fma.rn.f32x2 %0, %1, %2, %0;" : "+l"(d) : "l"(a), "l"(b));
}
__device__ __forceinline__ float lo2(ull v) {
    float x, y; asm("mov.b64 {%0, %1}, %2;" : "=f"(x), "=f"(y) : "l"(v)); return x;
}
__device__ __forceinline__ float hi2(ull v) {
    float x, y; asm("mov.b64 {%0, %1}, %2;" : "=f"(x), "=f"(y) : "l"(v)); return y;
}

// ---------------- scratch (device globals) ----------------
__device__ float g_T1[513 * 404];
__device__ float g_W12[513 * 400];
__device__ float g_wqkvx[(size_t)TB * 400];
__device__ float g_out[(size_t)TB * OSTRIDE];
__device__ float g_Wh2[25 * 300 * 4];       // k-blocked: [(kb*300+c)*4 + kk] = Wh[kb*4+kk][c]
__device__ float g_Wqkv2[25 * 164 * 4];     // k-blocked: [(kb*164+c)*4 + kk]

// ---------------- fold kernels ----------------
__global__ void fold1(const float* __restrict__ enc_W, const float* __restrict__ enc_b,
                      const float* __restrict__ Wk,    const float* __restrict__ Wv) {
    int idx = blockIdx.x * blockDim.x + threadIdx.x;
    if (idx >= 513 * 404) return;
    int r = idx / 404, c = idx % 404;
    const float* arow = (r < 512) ? (enc_W + (size_t)r * NINP) : enc_b;
    float acc = 0.f;
    if (c < 64) {
        #pragma unroll 4
        for (int k = 0; k < NINP; k++) acc += arow[k] * __ldg(&Wk[k * DK + c]);
    } else {
        int cc = c - 64;
        #pragma unroll 4
        for (int k = 0; k < NINP; k++) acc += arow[k] * __ldg(&Wv[k * ATT + cc]);
    }
    g_T1[idx] = acc;
}

__global__ void fold2(const float* __restrict__ Wq, const float* __restrict__ Wx) {
    int idx = blockIdx.x * blockDim.x + threadIdx.x;
    if (idx >= 513 * 400) return;
    int r = idx / 400, c = idx % 400;
    float acc = 0.f;
    if (c < 100) {
        const float* t1 = g_T1 + r * 404;
        const float* wq = Wq + c * DK;
        #pragma unroll 8
        for (int k = 0; k < DK; k++) acc += t1[k] * wq[k];
    } else {
        const float* t1 = g_T1 + r * 404 + 64;
        int cc = c - 100;
        #pragma unroll 4
        for (int k = 0; k < ATT; k++) acc += t1[k] * __ldg(&Wx[k * 300 + cc]);
    }
    g_W12[idx] = acc;
}

// k-blocked step-weight layouts (coalesced warp loads: lanes = consecutive cols)
__global__ void transposeW(const float* __restrict__ Wh,
                           const float* __restrict__ Wq2,
                           const float* __restrict__ Wk2,
                           const float* __restrict__ Wv2) {
    int i = blockIdx.x * blockDim.x + threadIdx.x;
    if (i < 300 * 100) {
        int k = i / 300, c = i % 300;
        g_Wh2[(((k >> 2) * 300) + c) * 4 + (k & 3)] = Wh[k * 300 + c];
    } else if (i < 300 * 100 + 164 * 100) {
        int j = i - 300 * 100;
        int k = j / 164, c = j % 164;
        float v;
        if (c < 32)      v = Wq2[k * 32 + c];
        else if (c < 64) v = Wk2[k * 32 + (c - 32)];
        else             v = Wv2[k * 100 + (c - 64)];
        g_Wqkv2[(((k >> 2) * 164) + c) * 4 + (k & 3)] = v;
    }
}

// ---------------- fp32 SGEMM, BK=16 double-buffered (R10, proven) ----------
// A: M x Astride (row-major). B: Kt x N (row-major); rows >= Kvalid read as 0.
__device__ __forceinline__ void sgemm_body(
    const float* __restrict__ A, const float* __restrict__ B,
    const float* __restrict__ bias, float* __restrict__ C,
    int M, int N, int Kt, int Kvalid, int Astride)
{
    __shared__ __align__(16) float As[2][16][128];
    __shared__ __align__(16) float Bs[2][16][128];
    const int tid = threadIdx.x;
    const int m0 = blockIdx.y * 128;
    const int n0 = blockIdx.x * 128;
    const int arow = tid >> 1, ac0 = (tid & 1) * 8;    // A loader: row, k-offset
    const int brow = tid >> 4, bc0 = (tid & 15) * 8;   // B loader: k-row, n-offset
    const int tm = (tid >> 4) * 8, tn = (tid & 15) * 8;
    const int Kc = Kt / 16;

    ull acc2[8][4];
    #pragma unroll
    for (int i = 0; i < 8; i++)
        #pragma unroll
        for (int j = 0; j < 4; j++) acc2[i][j] = 0ull;

    // ---- load chunk 0 directly into buffer 0
    {
        const float* ga = A + (size_t)(m0 + arow) * Astride + ac0;
        #pragma unroll
        for (int h = 0; h < 2; h++) {
            float4 av = *(const float4*)(ga + h * 4);
            As[0][ac0 + h * 4 + 0][arow] = av.x;
            As[0][ac0 + h * 4 + 1][arow] = av.y;
            As[0][ac0 + h * 4 + 2][arow] = av.z;
            As[0][ac0 + h * 4 + 3][arow] = av.w;
        }
        #pragma unroll
        for (int h = 0; h < 2; h++) {
            float4 bv = make_float4(0.f, 0.f, 0.f, 0.f);
            if (brow < Kvalid && n0 + bc0 + h * 4 < N)
                bv = *(const float4*)(B + (size_t)brow * N + n0 + bc0 + h * 4);
            *(float4*)&Bs[0][brow][bc0 + h * 4] = bv;
        }
    }
    __syncthreads();

    for (int kc = 0; kc < Kc; kc++) {
        float4 pa[2], pb[2];
        const bool more = (kc + 1 < Kc);
        if (more) {
            const int k1 = (kc + 1) * 16;
            const float* ga = A + (size_t)(m0 + arow) * Astride + k1 + ac0;
            #pragma unroll
            for (int h = 0; h < 2; h++) pa[h] = *(const float4*)(ga + h * 4);
            #pragma unroll
            for (int h = 0; h < 2; h++) {
                pb[h] = make_float4(0.f, 0.f, 0.f, 0.f);
                if (k1 + brow < Kvalid && n0 + bc0 + h * 4 < N)
                    pb[h] = *(const float4*)(B + (size_t)(k1 + brow) * N + n0 + bc0 + h * 4);
            }
        }

        const int cb = kc & 1;
        #pragma unroll
        for (int k = 0; k < 16; k++) {
            float4 a0 = *(const float4*)&As[cb][k][tm];
            float4 a1 = *(const float4*)&As[cb][k][tm + 4];
            ulonglong2 b01 = *(const ulonglong2*)&Bs[cb][k][tn];
            ulonglong2 b23 = *(const ulonglong2*)&Bs[cb][k][tn + 4];
            ull ad[8];
            ad[0] = dup2(a0.x); ad[1] = dup2(a0.y); ad[2] = dup2(a0.z); ad[3] = dup2(a0.w);
            ad[4] = dup2(a1.x); ad[5] = dup2(a1.y); ad[6] = dup2(a1.z); ad[7] = dup2(a1.w);
            #pragma unroll
            for (int i = 0; i < 8; i++) {
                fma2(acc2[i][0], ad[i], b01.x);
                fma2(acc2[i][1], ad[i], b01.y);
                fma2(acc2[i][2], ad[i], b23.x);
                fma2(acc2[i][3], ad[i], b23.y);
            }
        }

        if (more) {
            const int nb = cb ^ 1;
            #pragma unroll
            for (int h = 0; h < 2; h++) {
                As[nb][ac0 + h * 4 + 0][arow] = pa[h].x;
                As[nb][ac0 + h * 4 + 1][arow] = pa[h].y;
                As[nb][ac0 + h * 4 + 2][arow] = pa[h].z;
                As[nb][ac0 + h * 4 + 3][arow] = pa[h].w;
                *(float4*)&Bs[nb][brow][bc0 + h * 4] = pb[h];
            }
            __syncthreads();
        }
    }

    #pragma unroll
    for (int i = 0; i < 8; i++) {
        int m = m0 + tm + i;
        #pragma unroll
        for (int j2 = 0; j2 < 4; j2++) {
            int n = n0 + tn + j2 * 2;
            if (n < N) {
                float2 v;
                v.x = lo2(acc2[i][j2]) + bias[n + 0];
                v.y = hi2(acc2[i][j2]) + bias[n + 1];
                *(float2*)(C + (size_t)m * N + n) = v;
            }
        }
    }
}

__global__ __launch_bounds__(256) void gemm_wqkvx(const float* __restrict__ input) {
    sgemm_body(input, g_W12, g_W12 + 512 * 400, g_wqkvx, TB, 400, 512, 512, 512);
}

__global__ __launch_bounds__(256) void gemm_dec(const float* __restrict__ dec_W,
                                                const float* __restrict__ dec_b,
                                                float* __restrict__ C) {
    sgemm_body(g_out, dec_W, dec_b, C, TB, NTOK, OSTRIDE, NHID, OSTRIDE);
}

// ---------------- persistent steps: 4 batches/block, grid 128, 640 threads ----
struct StepSmem {
    float hb[100][32];
    float hn[100][32];
    float hg[24][301];
    float wqk[4][100];
    float vx[4][300];
    float sarr[24], parr[24], bm[24];
    float q2[24][33], k2[24][33];
    float v2[24][101];
    float p2[24][8];
};

__global__ __launch_bounds__(640, 1) void steps_persistent(
    const float* __restrict__ hidden,
    const float* __restrict__ masks,
    const float* __restrict__ gru_b,
    float* __restrict__ hT_out,
    float* __restrict__ bmask_out)
{
    extern __shared__ __align__(16) char smem_raw[];
    StepSmem& s = *reinterpret_cast<StepSmem*>(smem_raw);

    const int tid = threadIdx.x;
    const int b0 = blockIdx.x * 4;

    for (int i = tid; i < 2400; i += 640) {
        int bb = i / 600, j = i % 600;
        s.hb[j % 100][bb * 6 + j / 100] = hidden[(b0 + bb) * NHID + j];
    }
    // zero g_out pad columns for all t (once)
    for (int i = tid; i < T_ * 4 * (OSTRIDE - NHID); i += 640) {
        int t = i / (4 * (OSTRIDE - NHID));
        int r = i % (4 * (OSTRIDE - NHID));
        int bb = r / (OSTRIDE - NHID), c = r % (OSTRIDE - NHID);
        g_out[((size_t)t * B_ + b0 + bb) * OSTRIDE + NHID + c] = 0.f;
    }

    for (int t = 0; t < T_; t++) {
        __syncthreads();   // b1

        // ---- interval 1: hg = hb@Wh (raw)  |  warp19: prefetch+scores+topk
        if (tid < 600) {
            const int col = (tid < 300) ? tid : tid - 300;
            const int g   = (tid < 300) ? 0 : 12;
            ull acc[6] = {0, 0, 0, 0, 0, 0};
            for (int kb = 0; kb < 25; kb++) {
                float4 wv = *(const float4*)&g_Wh2[(kb * 300 + col) * 4];  // coalesced
                const int k = kb * 4;
                #pragma unroll
                for (int kk = 0; kk < 4; kk++) {
                    float w = (kk == 0) ? wv.x : (kk == 1) ? wv.y : (kk == 2) ? wv.z : wv.w;
                    ull wd = dup2(w);
                    const ulonglong2* hr = (const ulonglong2*)&s.hb[k + kk][g];
                    ulonglong2 h01 = hr[0], h23 = hr[1], h45 = hr[2];
                    fma2(acc[0], h01.x, wd); fma2(acc[1], h01.y, wd);
                    fma2(acc[2], h23.x, wd); fma2(acc[3], h23.y, wd);
                    fma2(acc[4], h45.x, wd); fma2(acc[5], h45.y, wd);
                }
            }
            #pragma unroll
            for (int p = 0; p < 6; p++) {
                s.hg[g + 2 * p][col]     = lo2(acc[p]);
                s.hg[g + 2 * p + 1][col] = hi2(acc[p]);
            }
        } else if (tid >= 608) {
            const int lane = tid - 608;
            const float* src = g_wqkvx + (size_t)(t * B_ + b0) * 400;
            for (int j = lane; j < 100; j += 32) {
                int bb = j / 25, c4 = j % 25;
                *(float4*)&s.wqk[bb][c4 * 4] = *(const float4*)(src + bb * 400 + c4 * 4);
            }
            for (int j = lane; j < 300; j += 32) {
                int bb = j / 75, c4 = j % 75;
                *(float4*)&s.vx[bb][c4 * 4] = *(const float4*)(src + bb * 400 + 100 + c4 * 4);
            }
            __syncwarp();
            if (lane < 24) {
                const int u = lane, bb = u / 6;
                const float m = masks[t * B_ + b0 + bb];
                const float* w = s.wqk[bb];
                float sc = 0.f;
                #pragma unroll 4
                for (int k = 0; k < 100; k++) sc += s.hb[k][u] * w[k];
                sc *= 0.125f * m;
                s.sarr[u] = sc;
                s.parr[u] = 1.f / (1.f + expf(-sc));
            }
            __syncwarp();
            if (lane < 24) {
                const int u = lane, bb = u / 6, n = u % 6;
                float sn = s.sarr[u];
                int cnt = 0;
                #pragma unroll
                for (int m2 = 0; m2 < 6; m2++) {
                    float sm = s.sarr[bb * 6 + m2];
                    if (sm > sn || (sm == sn && m2 < n)) cnt++;
                }
                float v = (cnt < TOPK_) ? 1.f : 0.f;
                s.bm[u] = v;
                bmask_out[(size_t)t * B_ * NB + (b0 + bb) * NB + n] = v;
            }
        }
        __syncthreads();   // b2

        // ---- phase C: GRU gates -> hn
        {
            const int u = tid & 31, jb = tid >> 5;
            if (u < 24) {
                const int bb = u / 6;
                const float m = masks[t * B_ + b0 + bb];
                const float p = s.parr[u];
                for (int j = jb; j < 100; j += 20) {
                    float xr = p * s.vx[bb][j]       + gru_b[j];
                    float xz = p * s.vx[bb][j + 100] + gru_b[j + 100];
                    float xn = p * s.vx[bb][j + 200] + gru_b[j + 200];
                    float r  = 1.f / (1.f + expf(-(xr + m * s.hg[u][j])));
                    float z  = 1.f / (1.f + expf(-(xz + m * s.hg[u][j + 100])));
                    float nn = tanhf(xn + r * (m * s.hg[u][j + 200]));
                    s.hn[j][u] = (1.f - z) * nn + z * (m * s.hb[j][u]);
                }
            }
        }
        __syncthreads();   // b3

        // ---- phase D: q2/k2/v2 = hn @ [Wq2|Wk2|Wv2]
        if (tid < 328) {
            const int col = (tid < 164) ? tid : tid - 164;
            const int g   = (tid < 164) ? 0 : 12;
            ull acc[6] = {0, 0, 0, 0, 0, 0};
            for (int kb = 0; kb < 25; kb++) {
                float4 wv = *(const float4*)&g_Wqkv2[(kb * 164 + col) * 4];  // coalesced
                const int k = kb * 4;
                #pragma unroll
                for (int kk = 0; kk < 4; kk++) {
                    float w = (kk == 0) ? wv.x : (kk == 1) ? wv.y : (kk == 2) ? wv.z : wv.w;
                    ull wd = dup2(w);
                    const ulonglong2* hr = (const ulonglong2*)&s.hn[k + kk][g];
                    ulonglong2 h01 = hr[0], h23 = hr[1], h45 = hr[2];
                    fma2(acc[0], h01.x, wd); fma2(acc[1], h01.y, wd);
                    fma2(acc[2], h23.x, wd); fma2(acc[3], h23.y, wd);
                    fma2(acc[4], h45.x, wd); fma2(acc[5], h45.y, wd);
                }
            }
            #pragma unroll
            for (int p = 0; p < 6; p++) {
                float x = lo2(acc[p]), y = hi2(acc[p]);
                int u0 = g + 2 * p, u1 = g + 2 * p + 1;
                if (col < 32)      { s.q2[u0][col] = x;      s.q2[u1][col] = y; }
                else if (col < 64) { s.k2[u0][col - 32] = x; s.k2[u1][col - 32] = y; }
                else               { s.v2[u0][col - 64] = x; s.v2[u1][col - 64] = y; }
            }
        }
        __syncthreads();   // b4

        // ---- phase E: attention-2 scores + softmax
        if (tid < 128) {
            const int wd = tid >> 5, lane = tid & 31;
            const int bb = wd;
            for (int job = lane; job < 36; job += 32) {
                int n = job / 6, m2 = job % 6;
                const float* qr = s.q2[bb * 6 + n];
                const float* kr = s.k2[bb * 6 + m2];
                float sc = 0.f;
                #pragma unroll
                for (int d = 0; d < 32; d++) sc += qr[d] * kr[d];
                s.p2[bb * 6 + n][m2] = sc * 0.17677669529663687f;
            }
            __syncwarp();
            if (lane < 6) {
                const int u = bb * 6 + lane;
                float mx = -1e30f;
                #pragma unroll
                for (int m2 = 0; m2 < 6; m2++) mx = fmaxf(mx, s.p2[u][m2]);
                float e[6], sum = 0.f;
                #pragma unroll
                for (int m2 = 0; m2 < 6; m2++) { e[m2] = expf(s.p2[u][m2] - mx); sum += e[m2]; }
                float inv = 1.f / sum;
                #pragma unroll
                for (int m2 = 0; m2 < 6; m2++) s.p2[u][m2] = e[m2] * inv;
            }
        }
        __syncthreads();   // b5

        // ---- phase F: hc = hn + p2@v2; blend; write state + history
        {
            const int u = tid & 31, jb = tid >> 5;
            if (u < 24) {
                const int bb = u / 6;
                const float m = masks[t * B_ + b0 + bb];
                const float bmu = s.bm[u];
                float pr[6];
                #pragma unroll
                for (int m2 = 0; m2 < 6; m2++) pr[m2] = s.p2[u][m2];
                for (int j = jb; j < 100; j += 20) {
                    float acc = s.hn[j][u];
                    #pragma unroll
                    for (int m2 = 0; m2 < 6; m2++) acc += pr[m2] * s.v2[bb * 6 + m2][j];
                    float res = (bmu > 0.5f) ? acc : (m * s.hb[j][u]);
                    s.hb[j][u] = res;
                    g_out[((size_t)t * B_ + b0 + bb) * OSTRIDE + (u % 6) * 100 + j] = res;
                }
            }
        }
    }

    __syncthreads();
    for (int i = tid; i < 2400; i += 640) {
        int bb = i / 600, j = i % 600;
        hT_out[(b0 + bb) * NHID + j] = s.hb[j % 100][bb * 6 + j / 100];
    }
}

// ---------------- launch ----------------
extern "C" void kernel_launch(void* const* d_in, const int* in_sizes, int n_in,
                              void* d_out, int out_size) {
    const float* input  = (const float*)d_in[0];
    const float* hidden = (const float*)d_in[1];
    const float* masks  = (const float*)d_in[2];
    const float* enc_W  = (const float*)d_in[3];
    const float* enc_b  = (const float*)d_in[4];
    const float* Wq     = (const float*)d_in[5];
    const float* Wk     = (const float*)d_in[6];
    const float* Wv     = (const float*)d_in[7];
    const float* Wx     = (const float*)d_in[8];
    const float* Wh     = (const float*)d_in[9];
    const float* gru_b  = (const float*)d_in[10];
    const float* Wq2    = (const float*)d_in[11];
    const float* Wk2    = (const float*)d_in[12];
    const float* Wv2    = (const float*)d_in[13];
    const float* dec_W  = (const float*)d_in[14];
    const float* dec_b  = (const float*)d_in[15];
    float* out = (float*)d_out;

    static int attr_set = 0;
    int step_smem = (int)sizeof(StepSmem);
    if (!attr_set) {
        cudaFuncSetAttribute(steps_persistent,
                             cudaFuncAttributeMaxDynamicSharedMemorySize, step_smem);
        attr_set = 1;
    }

    fold1<<<(513 * 404 + 255) / 256, 256>>>(enc_W, enc_b, Wk, Wv);
    fold2<<<(513 * 400 + 255) / 256, 256>>>(Wq, Wx);
    transposeW<<<(300 * 100 + 164 * 100 + 255) / 256, 256>>>(Wh, Wq2, Wk2, Wv2);

    gemm_wqkvx<<<dim3(4, TB / 128), 256>>>(input);

    float* hT_out    = out + DEC_OFF;
    float* bmask_out = out + DEC_OFF + B_ * NHID;
    steps_persistent<<<B_ / 4, 640, step_smem>>>(hidden, masks, gru_b, hT_out, bmask_out);

    gemm_dec<<<dim3(4, TB / 128), 256>>>(dec_W, dec_b, out);
}

// round 13
// speedup vs baseline: 1.2583x; 1.0152x over previous
#include <cuda_runtime.h>
#include <math.h>
#include <stdint.h>

#define T_    64
#define B_    512
#define NTOK  512
#define NINP  600
#define NHID  600
#define NB    6
#define TOPK_ 4
#define BS_   100
#define ATT   340
#define DK    64
#define DC    32

#define TB    (T_ * B_)              // 32768
#define DEC_OFF   (TB * NTOK)        // 16777216
#define OSTRIDE   608                // g_out row stride (16-multiple, 600 valid)

typedef unsigned long long ull;

// ---------------- f32x2 packed helpers ----------------
__device__ __forceinline__ ull dup2(float x) {
    ull r; asm("mov.b64 %0, {%1, %1};" : "=l"(r) : "f"(x)); return r;
}
__device__ __forceinline__ void fma2(ull &d, ull a, ull b) {
    asm("fma.rn.f32x2 %0, %1, %2, %0;" : "+l"(d) : "l"(a), "l"(b));
}
__device__ __forceinline__ float lo2(ull v) {
    float x, y; asm("mov.b64 {%0, %1}, %2;" : "=f"(x), "=f"(y) : "l"(v)); return x;
}
__device__ __forceinline__ float hi2(ull v) {
    float x, y; asm("mov.b64 {%0, %1}, %2;" : "=f"(x), "=f"(y) : "l"(v)); return y;
}

// ---------------- scratch (device globals) ----------------
__device__ float g_T1[513 * 404];
__device__ float g_W12[513 * 400];
__device__ float g_wqkvx[(size_t)TB * 400];
__device__ float g_out[(size_t)TB * OSTRIDE];
__device__ float g_Wh2[25 * 300 * 4];       // k-blocked: [(kb*300+c)*4 + kk] = Wh[kb*4+kk][c]
__device__ float g_Wqkv2[25 * 164 * 4];     // k-blocked: [(kb*164+c)*4 + kk]

// ---------------- fold kernels ----------------
__global__ void fold1(const float* __restrict__ enc_W, const float* __restrict__ enc_b,
                      const float* __restrict__ Wk,    const float* __restrict__ Wv) {
    int idx = blockIdx.x * blockDim.x + threadIdx.x;
    if (idx >= 513 * 404) return;
    int r = idx / 404, c = idx % 404;
    const float* arow = (r < 512) ? (enc_W + (size_t)r * NINP) : enc_b;
    float acc = 0.f;
    if (c < 64) {
        #pragma unroll 4
        for (int k = 0; k < NINP; k++) acc += arow[k] * __ldg(&Wk[k * DK + c]);
    } else {
        int cc = c - 64;
        #pragma unroll 4
        for (int k = 0; k < NINP; k++) acc += arow[k] * __ldg(&Wv[k * ATT + cc]);
    }
    g_T1[idx] = acc;
}

__global__ void fold2(const float* __restrict__ Wq, const float* __restrict__ Wx) {
    int idx = blockIdx.x * blockDim.x + threadIdx.x;
    if (idx >= 513 * 400) return;
    int r = idx / 400, c = idx % 400;
    float acc = 0.f;
    if (c < 100) {
        const float* t1 = g_T1 + r * 404;
        const float* wq = Wq + c * DK;
        #pragma unroll 8
        for (int k = 0; k < DK; k++) acc += t1[k] * wq[k];
    } else {
        const float* t1 = g_T1 + r * 404 + 64;
        int cc = c - 100;
        #pragma unroll 4
        for (int k = 0; k < ATT; k++) acc += t1[k] * __ldg(&Wx[k * 300 + cc]);
    }
    g_W12[idx] = acc;
}

// k-blocked step-weight layouts (coalesced warp loads: lanes = consecutive cols)
__global__ void transposeW(const float* __restrict__ Wh,
                           const float* __restrict__ Wq2,
                           const float* __restrict__ Wk2,
                           const float* __restrict__ Wv2) {
    int i = blockIdx.x * blockDim.x + threadIdx.x;
    if (i < 300 * 100) {
        int k = i / 300, c = i % 300;
        g_Wh2[(((k >> 2) * 300) + c) * 4 + (k & 3)] = Wh[k * 300 + c];
    } else if (i < 300 * 100 + 164 * 100) {
        int j = i - 300 * 100;
        int k = j / 164, c = j % 164;
        float v;
        if (c < 32)      v = Wq2[k * 32 + c];
        else if (c < 64) v = Wk2[k * 32 + (c - 32)];
        else             v = Wv2[k * 100 + (c - 64)];
        g_Wqkv2[(((k >> 2) * 164) + c) * 4 + (k & 3)] = v;
    }
}

// ---------------- fp32 SGEMM, BK=16 double-buffered (R10, proven) ----------
// A: M x Astride (row-major). B: Kt x N (row-major); rows >= Kvalid read as 0.
__device__ __forceinline__ void sgemm_body(
    const float* __restrict__ A, const float* __restrict__ B,
    const float* __restrict__ bias, float* __restrict__ C,
    int M, int N, int Kt, int Kvalid, int Astride)
{
    __shared__ __align__(16) float As[2][16][128];
    __shared__ __align__(16) float Bs[2][16][128];
    const int tid = threadIdx.x;
    const int m0 = blockIdx.y * 128;
    const int n0 = blockIdx.x * 128;
    const int arow = tid >> 1, ac0 = (tid & 1) * 8;    // A loader: row, k-offset
    const int brow = tid >> 4, bc0 = (tid & 15) * 8;   // B loader: k-row, n-offset
    const int tm = (tid >> 4) * 8, tn = (tid & 15) * 8;
    const int Kc = Kt / 16;

    ull acc2[8][4];
    #pragma unroll
    for (int i = 0; i < 8; i++)
        #pragma unroll
        for (int j = 0; j < 4; j++) acc2[i][j] = 0ull;

    // ---- load chunk 0 directly into buffer 0
    {
        const float* ga = A + (size_t)(m0 + arow) * Astride + ac0;
        #pragma unroll
        for (int h = 0; h < 2; h++) {
            float4 av = *(const float4*)(ga + h * 4);
            As[0][ac0 + h * 4 + 0][arow] = av.x;
            As[0][ac0 + h * 4 + 1][arow] = av.y;
            As[0][ac0 + h * 4 + 2][arow] = av.z;
            As[0][ac0 + h * 4 + 3][arow] = av.w;
        }
        #pragma unroll
        for (int h = 0; h < 2; h++) {
            float4 bv = make_float4(0.f, 0.f, 0.f, 0.f);
            if (brow < Kvalid && n0 + bc0 + h * 4 < N)
                bv = *(const float4*)(B + (size_t)brow * N + n0 + bc0 + h * 4);
            *(float4*)&Bs[0][brow][bc0 + h * 4] = bv;
        }
    }
    __syncthreads();

    for (int kc = 0; kc < Kc; kc++) {
        float4 pa[2], pb[2];
        const bool more = (kc + 1 < Kc);
        if (more) {
            const int k1 = (kc + 1) * 16;
            const float* ga = A + (size_t)(m0 + arow) * Astride + k1 + ac0;
            #pragma unroll
            for (int h = 0; h < 2; h++) pa[h] = *(const float4*)(ga + h * 4);
            #pragma unroll
            for (int h = 0; h < 2; h++) {
                pb[h] = make_float4(0.f, 0.f, 0.f, 0.f);
                if (k1 + brow < Kvalid && n0 + bc0 + h * 4 < N)
                    pb[h] = *(const float4*)(B + (size_t)(k1 + brow) * N + n0 + bc0 + h * 4);
            }
        }

        const int cb = kc & 1;
        #pragma unroll
        for (int k = 0; k < 16; k++) {
            float4 a0 = *(const float4*)&As[cb][k][tm];
            float4 a1 = *(const float4*)&As[cb][k][tm + 4];
            ulonglong2 b01 = *(const ulonglong2*)&Bs[cb][k][tn];
            ulonglong2 b23 = *(const ulonglong2*)&Bs[cb][k][tn + 4];
            ull ad[8];
            ad[0] = dup2(a0.x); ad[1] = dup2(a0.y); ad[2] = dup2(a0.z); ad[3] = dup2(a0.w);
            ad[4] = dup2(a1.x); ad[5] = dup2(a1.y); ad[6] = dup2(a1.z); ad[7] = dup2(a1.w);
            #pragma unroll
            for (int i = 0; i < 8; i++) {
                fma2(acc2[i][0], ad[i], b01.x);
                fma2(acc2[i][1], ad[i], b01.y);
                fma2(acc2[i][2], ad[i], b23.x);
                fma2(acc2[i][3], ad[i], b23.y);
            }
        }

        if (more) {
            const int nb = cb ^ 1;
            #pragma unroll
            for (int h = 0; h < 2; h++) {
                As[nb][ac0 + h * 4 + 0][arow] = pa[h].x;
                As[nb][ac0 + h * 4 + 1][arow] = pa[h].y;
                As[nb][ac0 + h * 4 + 2][arow] = pa[h].z;
                As[nb][ac0 + h * 4 + 3][arow] = pa[h].w;
                *(float4*)&Bs[nb][brow][bc0 + h * 4] = pb[h];
            }
            __syncthreads();
        }
    }

    #pragma unroll
    for (int i = 0; i < 8; i++) {
        int m = m0 + tm + i;
        #pragma unroll
        for (int j2 = 0; j2 < 4; j2++) {
            int n = n0 + tn + j2 * 2;
            if (n < N) {
                float2 v;
                v.x = lo2(acc2[i][j2]) + bias[n + 0];
                v.y = hi2(acc2[i][j2]) + bias[n + 1];
                *(float2*)(C + (size_t)m * N + n) = v;
            }
        }
    }
}

__global__ __launch_bounds__(256) void gemm_wqkvx(const float* __restrict__ input) {
    sgemm_body(input, g_W12, g_W12 + 512 * 400, g_wqkvx, TB, 400, 512, 512, 512);
}

__global__ __launch_bounds__(256) void gemm_dec(const float* __restrict__ dec_W,
                                                const float* __restrict__ dec_b,
                                                float* __restrict__ C) {
    sgemm_body(g_out, dec_W, dec_b, C, TB, NTOK, OSTRIDE, NHID, OSTRIDE);
}

// ---------------- persistent steps: 4 batches/block, grid 128, 640 threads ----
struct StepSmem {
    float wh[25 * 300 * 4];    // smem-resident copy of g_Wh2 (120 KB)
    float hb[100][32];
    float hn[100][32];
    float hg[24][301];
    float wqk[4][100];
    float vx[4][300];
    float sarr[24], parr[24], bm[24];
    float q2[24][33], k2[24][33];
    float v2[24][101];
    float p2[24][8];
};

__global__ __launch_bounds__(640, 1) void steps_persistent(
    const float* __restrict__ hidden,
    const float* __restrict__ masks,
    const float* __restrict__ gru_b,
    float* __restrict__ hT_out,
    float* __restrict__ bmask_out)
{
    extern __shared__ __align__(16) char smem_raw[];
    StepSmem& s = *reinterpret_cast<StepSmem*>(smem_raw);

    const int tid = threadIdx.x;
    const int b0 = blockIdx.x * 4;

    // load Wh2 into smem (coalesced float4), plus initial state
    {
        float4* dst = (float4*)s.wh;
        const float4* src = (const float4*)g_Wh2;
        for (int i = tid; i < 25 * 300; i += 640) dst[i] = src[i];
    }
    for (int i = tid; i < 2400; i += 640) {
        int bb = i / 600, j = i % 600;
        s.hb[j % 100][bb * 6 + j / 100] = hidden[(b0 + bb) * NHID + j];
    }
    // zero g_out pad columns for all t (once)
    for (int i = tid; i < T_ * 4 * (OSTRIDE - NHID); i += 640) {
        int t = i / (4 * (OSTRIDE - NHID));
        int r = i % (4 * (OSTRIDE - NHID));
        int bb = r / (OSTRIDE - NHID), c = r % (OSTRIDE - NHID);
        g_out[((size_t)t * B_ + b0 + bb) * OSTRIDE + NHID + c] = 0.f;
    }

    for (int t = 0; t < T_; t++) {
        __syncthreads();   // b1 (also covers wh/hb initial loads at t=0)

        // ---- interval 1: hg = hb@Wh (weights from smem) | warp19: prefetch+scores+topk
        if (tid < 600) {
            const int col = (tid < 300) ? tid : tid - 300;
            const int g   = (tid < 300) ? 0 : 12;
            ull acc[6] = {0, 0, 0, 0, 0, 0};
            for (int kb = 0; kb < 25; kb++) {
                float4 wv = *(const float4*)&s.wh[(kb * 300 + col) * 4];   // LDS, conflict-free
                const int k = kb * 4;
                #pragma unroll
                for (int kk = 0; kk < 4; kk++) {
                    float w = (kk == 0) ? wv.x : (kk == 1) ? wv.y : (kk == 2) ? wv.z : wv.w;
                    ull wd = dup2(w);
                    const ulonglong2* hr = (const ulonglong2*)&s.hb[k + kk][g];
                    ulonglong2 h01 = hr[0], h23 = hr[1], h45 = hr[2];
                    fma2(acc[0], h01.x, wd); fma2(acc[1], h01.y, wd);
                    fma2(acc[2], h23.x, wd); fma2(acc[3], h23.y, wd);
                    fma2(acc[4], h45.x, wd); fma2(acc[5], h45.y, wd);
                }
            }
            #pragma unroll
            for (int p = 0; p < 6; p++) {
                s.hg[g + 2 * p][col]     = lo2(acc[p]);
                s.hg[g + 2 * p + 1][col] = hi2(acc[p]);
            }
        } else if (tid >= 608) {
            const int lane = tid - 608;
            const float* src = g_wqkvx + (size_t)(t * B_ + b0) * 400;
            for (int j = lane; j < 100; j += 32) {
                int bb = j / 25, c4 = j % 25;
                *(float4*)&s.wqk[bb][c4 * 4] = *(const float4*)(src + bb * 400 + c4 * 4);
            }
            for (int j = lane; j < 300; j += 32) {
                int bb = j / 75, c4 = j % 75;
                *(float4*)&s.vx[bb][c4 * 4] = *(const float4*)(src + bb * 400 + 100 + c4 * 4);
            }
            __syncwarp();
            if (lane < 24) {
                const int u = lane, bb = u / 6;
                const float m = masks[t * B_ + b0 + bb];
                const float* w = s.wqk[bb];
                float sc = 0.f;
                #pragma unroll 4
                for (int k = 0; k < 100; k++) sc += s.hb[k][u] * w[k];
                sc *= 0.125f * m;
                s.sarr[u] = sc;
                s.parr[u] = 1.f / (1.f + expf(-sc));
            }
            __syncwarp();
            if (lane < 24) {
                const int u = lane, bb = u / 6, n = u % 6;
                float sn = s.sarr[u];
                int cnt = 0;
                #pragma unroll
                for (int m2 = 0; m2 < 6; m2++) {
                    float sm = s.sarr[bb * 6 + m2];
                    if (sm > sn || (sm == sn && m2 < n)) cnt++;
                }
                float v = (cnt < TOPK_) ? 1.f : 0.f;
                s.bm[u] = v;
                bmask_out[(size_t)t * B_ * NB + (b0 + bb) * NB + n] = v;
            }
        }
        __syncthreads();   // b2

        // ---- phase C: GRU gates -> hn
        {
            const int u = tid & 31, jb = tid >> 5;
            if (u < 24) {
                const int bb = u / 6;
                const float m = masks[t * B_ + b0 + bb];
                const float p = s.parr[u];
                for (int j = jb; j < 100; j += 20) {
                    float xr = p * s.vx[bb][j]       + gru_b[j];
                    float xz = p * s.vx[bb][j + 100] + gru_b[j + 100];
                    float xn = p * s.vx[bb][j + 200] + gru_b[j + 200];
                    float r  = 1.f / (1.f + expf(-(xr + m * s.hg[u][j])));
                    float z  = 1.f / (1.f + expf(-(xz + m * s.hg[u][j + 100])));
                    float nn = tanhf(xn + r * (m * s.hg[u][j + 200]));
                    s.hn[j][u] = (1.f - z) * nn + z * (m * s.hb[j][u]);
                }
            }
        }
        __syncthreads();   // b3

        // ---- phase D: q2/k2/v2 = hn @ [Wq2|Wk2|Wv2] (weights via LDG, L2-resident)
        if (tid < 328) {
            const int col = (tid < 164) ? tid : tid - 164;
            const int g   = (tid < 164) ? 0 : 12;
            ull acc[6] = {0, 0, 0, 0, 0, 0};
            for (int kb = 0; kb < 25; kb++) {
                float4 wv = *(const float4*)&g_Wqkv2[(kb * 164 + col) * 4];  // coalesced
                const int k = kb * 4;
                #pragma unroll
                for (int kk = 0; kk < 4; kk++) {
                    float w = (kk == 0) ? wv.x : (kk == 1) ? wv.y : (kk == 2) ? wv.z : wv.w;
                    ull wd = dup2(w);
                    const ulonglong2* hr = (const ulonglong2*)&s.hn[k + kk][g];
                    ulonglong2 h01 = hr[0], h23 = hr[1], h45 = hr[2];
                    fma2(acc[0], h01.x, wd); fma2(acc[1], h01.y, wd);
                    fma2(acc[2], h23.x, wd); fma2(acc[3], h23.y, wd);
                    fma2(acc[4], h45.x, wd); fma2(acc[5], h45.y, wd);
                }
            }
            #pragma unroll
            for (int p = 0; p < 6; p++) {
                float x = lo2(acc[p]), y = hi2(acc[p]);
                int u0 = g + 2 * p, u1 = g + 2 * p + 1;
                if (col < 32)      { s.q2[u0][col] = x;      s.q2[u1][col] = y; }
                else if (col < 64) { s.k2[u0][col - 32] = x; s.k2[u1][col - 32] = y; }
                else               { s.v2[u0][col - 64] = x; s.v2[u1][col - 64] = y; }
            }
        }
        __syncthreads();   // b4

        // ---- phase E: attention-2 scores + softmax
        if (tid < 128) {
            const int wd = tid >> 5, lane = tid & 31;
            const int bb = wd;
            for (int job = lane; job < 36; job += 32) {
                int n = job / 6, m2 = job % 6;
                const float* qr = s.q2[bb * 6 + n];
                const float* kr = s.k2[bb * 6 + m2];
                float sc = 0.f;
                #pragma unroll
                for (int d = 0; d < 32; d++) sc += qr[d] * kr[d];
                s.p2[bb * 6 + n][m2] = sc * 0.17677669529663687f;
            }
            __syncwarp();
            if (lane < 6) {
                const int u = bb * 6 + lane;
                float mx = -1e30f;
                #pragma unroll
                for (int m2 = 0; m2 < 6; m2++) mx = fmaxf(mx, s.p2[u][m2]);
                float e[6], sum = 0.f;
                #pragma unroll
                for (int m2 = 0; m2 < 6; m2++) { e[m2] = expf(s.p2[u][m2] - mx); sum += e[m2]; }
                float inv = 1.f / sum;
                #pragma unroll
                for (int m2 = 0; m2 < 6; m2++) s.p2[u][m2] = e[m2] * inv;
            }
        }
        __syncthreads();   // b5

        // ---- phase F: hc = hn + p2@v2; blend; write state + history
        {
            const int u = tid & 31, jb = tid >> 5;
            if (u < 24) {
                const int bb = u / 6;
                const float m = masks[t * B_ + b0 + bb];
                const float bmu = s.bm[u];
                float pr[6];
                #pragma unroll
                for (int m2 = 0; m2 < 6; m2++) pr[m2] = s.p2[u][m2];
                for (int j = jb; j < 100; j += 20) {
                    float acc = s.hn[j][u];
                    #pragma unroll
                    for (int m2 = 0; m2 < 6; m2++) acc += pr[m2] * s.v2[bb * 6 + m2][j];
                    float res = (bmu > 0.5f) ? acc : (m * s.hb[j][u]);
                    s.hb[j][u] = res;
                    g_out[((size_t)t * B_ + b0 + bb) * OSTRIDE + (u % 6) * 100 + j] = res;
                }
            }
        }
    }

    __syncthreads();
    for (int i = tid; i < 2400; i += 640) {
        int bb = i / 600, j = i % 600;
        hT_out[(b0 + bb) * NHID + j] = s.hb[j % 100][bb * 6 + j / 100];
    }
}

// ---------------- launch ----------------
extern "C" void kernel_launch(void* const* d_in, const int* in_sizes, int n_in,
                              void* d_out, int out_size) {
    const float* input  = (const float*)d_in[0];
    const float* hidden = (const float*)d_in[1];
    const float* masks  = (const float*)d_in[2];
    const float* enc_W  = (const float*)d_in[3];
    const float* enc_b  = (const float*)d_in[4];
    const float* Wq     = (const float*)d_in[5];
    const float* Wk     = (const float*)d_in[6];
    const float* Wv     = (const float*)d_in[7];
    const float* Wx     = (const float*)d_in[8];
    const float* Wh     = (const float*)d_in[9];
    const float* gru_b  = (const float*)d_in[10];
    const float* Wq2    = (const float*)d_in[11];
    const float* Wk2    = (const float*)d_in[12];
    const float* Wv2    = (const float*)d_in[13];
    const float* dec_W  = (const float*)d_in[14];
    const float* dec_b  = (const float*)d_in[15];
    float* out = (float*)d_out;

    static int attr_set = 0;
    int step_smem = (int)sizeof(StepSmem);
    if (!attr_set) {
        cudaFuncSetAttribute(steps_persistent,
                             cudaFuncAttributeMaxDynamicSharedMemorySize, step_smem);
        attr_set = 1;
    }

    fold1<<<(513 * 404 + 255) / 256, 256>>>(enc_W, enc_b, Wk, Wv);
    fold2<<<(513 * 400 + 255) / 256, 256>>>(Wq, Wx);
    transposeW<<<(300 * 100 + 164 * 100 + 255) / 256, 256>>>(Wh, Wq2, Wk2, Wv2);

    gemm_wqkvx<<<dim3(4, TB / 128), 256>>>(input);

    float* hT_out    = out + DEC_OFF;
    float* bmask_out = out + DEC_OFF + B_ * NHID;
    steps_persistent<<<B_ / 4, 640, step_smem>>>(hidden, masks, gru_b, hT_out, bmask_out);

    gemm_dec<<<dim3(4, TB / 128), 256>>>(dec_W, dec_b, out);
}

// round 15
// speedup vs baseline: 1.2848x; 1.0211x over previous
#include <cuda_runtime.h>
#include <math.h>
#include <stdint.h>

#define T_    64
#define B_    512
#define NTOK  512
#define NINP  600
#define NHID  600
#define NB    6
#define TOPK_ 4
#define BS_   100
#define ATT   340
#define DK    64
#define DC    32

#define TB    (T_ * B_)              // 32768
#define DEC_OFF   (TB * NTOK)        // 16777216
#define OSTRIDE   608                // g_out row stride (16-multiple, 600 valid)

typedef unsigned long long ull;

// ---------------- f32x2 packed helpers ----------------
__device__ __forceinline__ ull dup2(float x) {
    ull r; asm("mov.b64 %0, {%1, %1};" : "=l"(r) : "f"(x)); return r;
}
__device__ __forceinline__ void fma2(ull &d, ull a, ull b) {
    asm("fma.rn.f32x2 %0, %1, %2, %0;" : "+l"(d) : "l"(a), "l"(b));
}
__device__ __forceinline__ float lo2(ull v) {
    float x, y; asm("mov.b64 {%0, %1}, %2;" : "=f"(x), "=f"(y) : "l"(v)); return x;
}
__device__ __forceinline__ float hi2(ull v) {
    float x, y; asm("mov.b64 {%0, %1}, %2;" : "=f"(x), "=f"(y) : "l"(v)); return y;
}

// ---------------- scratch (device globals) ----------------
__device__ float g_T1[513 * 404];
__device__ float g_W12[513 * 400];
__device__ float g_wqkvx[(size_t)TB * 400];
__device__ float g_out[(size_t)TB * OSTRIDE];
__device__ float g_Wh2[25 * 300 * 4];       // k-blocked: [(kb*300+c)*4 + kk] = Wh[kb*4+kk][c]
__device__ float g_Wqkv2[25 * 164 * 4];     // k-blocked: [(kb*164+c)*4 + kk]

// ---------------- fold kernels ----------------
__global__ void fold1(const float* __restrict__ enc_W, const float* __restrict__ enc_b,
                      const float* __restrict__ Wk,    const float* __restrict__ Wv) {
    int idx = blockIdx.x * blockDim.x + threadIdx.x;
    if (idx >= 513 * 404) return;
    int r = idx / 404, c = idx % 404;
    const float* arow = (r < 512) ? (enc_W + (size_t)r * NINP) : enc_b;
    float acc = 0.f;
    if (c < 64) {
        #pragma unroll 4
        for (int k = 0; k < NINP; k++) acc += arow[k] * __ldg(&Wk[k * DK + c]);
    } else {
        int cc = c - 64;
        #pragma unroll 4
        for (int k = 0; k < NINP; k++) acc += arow[k] * __ldg(&Wv[k * ATT + cc]);
    }
    g_T1[idx] = acc;
}

__global__ void fold2(const float* __restrict__ Wq, const float* __restrict__ Wx) {
    int idx = blockIdx.x * blockDim.x + threadIdx.x;
    if (idx >= 513 * 400) return;
    int r = idx / 400, c = idx % 400;
    float acc = 0.f;
    if (c < 100) {
        const float* t1 = g_T1 + r * 404;
        const float* wq = Wq + c * DK;
        #pragma unroll 8
        for (int k = 0; k < DK; k++) acc += t1[k] * wq[k];
    } else {
        const float* t1 = g_T1 + r * 404 + 64;
        int cc = c - 100;
        #pragma unroll 4
        for (int k = 0; k < ATT; k++) acc += t1[k] * __ldg(&Wx[k * 300 + cc]);
    }
    g_W12[idx] = acc;
}

// k-blocked step-weight layouts (coalesced warp loads: lanes = consecutive cols)
__global__ void transposeW(const float* __restrict__ Wh,
                           const float* __restrict__ Wq2,
                           const float* __restrict__ Wk2,
                           const float* __restrict__ Wv2) {
    int i = blockIdx.x * blockDim.x + threadIdx.x;
    if (i < 300 * 100) {
        int k = i / 300, c = i % 300;
        g_Wh2[(((k >> 2) * 300) + c) * 4 + (k & 3)] = Wh[k * 300 + c];
    } else if (i < 300 * 100 + 164 * 100) {
        int j = i - 300 * 100;
        int k = j / 164, c = j % 164;
        float v;
        if (c < 32)      v = Wq2[k * 32 + c];
        else if (c < 64) v = Wk2[k * 32 + (c - 32)];
        else             v = Wv2[k * 100 + (c - 64)];
        g_Wqkv2[(((k >> 2) * 164) + c) * 4 + (k & 3)] = v;
    }
}

// ---------------- fp32 SGEMM, BK=16 double-buffered (proven, frozen) --------
__device__ __forceinline__ void sgemm_body(
    const float* __restrict__ A, const float* __restrict__ B,
    const float* __restrict__ bias, float* __restrict__ C,
    int M, int N, int Kt, int Kvalid, int Astride)
{
    __shared__ __align__(16) float As[2][16][128];
    __shared__ __align__(16) float Bs[2][16][128];
    const int tid = threadIdx.x;
    const int m0 = blockIdx.y * 128;
    const int n0 = blockIdx.x * 128;
    const int arow = tid >> 1, ac0 = (tid & 1) * 8;
    const int brow = tid >> 4, bc0 = (tid & 15) * 8;
    const int tm = (tid >> 4) * 8, tn = (tid & 15) * 8;
    const int Kc = Kt / 16;

    ull acc2[8][4];
    #pragma unroll
    for (int i = 0; i < 8; i++)
        #pragma unroll
        for (int j = 0; j < 4; j++) acc2[i][j] = 0ull;

    {
        const float* ga = A + (size_t)(m0 + arow) * Astride + ac0;
        #pragma unroll
        for (int h = 0; h < 2; h++) {
            float4 av = *(const float4*)(ga + h * 4);
            As[0][ac0 + h * 4 + 0][arow] = av.x;
            As[0][ac0 + h * 4 + 1][arow] = av.y;
            As[0][ac0 + h * 4 + 2][arow] = av.z;
            As[0][ac0 + h * 4 + 3][arow] = av.w;
        }
        #pragma unroll
        for (int h = 0; h < 2; h++) {
            float4 bv = make_float4(0.f, 0.f, 0.f, 0.f);
            if (brow < Kvalid && n0 + bc0 + h * 4 < N)
                bv = *(const float4*)(B + (size_t)brow * N + n0 + bc0 + h * 4);
            *(float4*)&Bs[0][brow][bc0 + h * 4] = bv;
        }
    }
    __syncthreads();

    for (int kc = 0; kc < Kc; kc++) {
        float4 pa[2], pb[2];
        const bool more = (kc + 1 < Kc);
        if (more) {
            const int k1 = (kc + 1) * 16;
            const float* ga = A + (size_t)(m0 + arow) * Astride + k1 + ac0;
            #pragma unroll
            for (int h = 0; h < 2; h++) pa[h] = *(const float4*)(ga + h * 4);
            #pragma unroll
            for (int h = 0; h < 2; h++) {
                pb[h] = make_float4(0.f, 0.f, 0.f, 0.f);
                if (k1 + brow < Kvalid && n0 + bc0 + h * 4 < N)
                    pb[h] = *(const float4*)(B + (size_t)(k1 + brow) * N + n0 + bc0 + h * 4);
            }
        }

        const int cb = kc & 1;
        #pragma unroll
        for (int k = 0; k < 16; k++) {
            float4 a0 = *(const float4*)&As[cb][k][tm];
            float4 a1 = *(const float4*)&As[cb][k][tm + 4];
            ulonglong2 b01 = *(const ulonglong2*)&Bs[cb][k][tn];
            ulonglong2 b23 = *(const ulonglong2*)&Bs[cb][k][tn + 4];
            ull ad[8];
            ad[0] = dup2(a0.x); ad[1] = dup2(a0.y); ad[2] = dup2(a0.z); ad[3] = dup2(a0.w);
            ad[4] = dup2(a1.x); ad[5] = dup2(a1.y); ad[6] = dup2(a1.z); ad[7] = dup2(a1.w);
            #pragma unroll
            for (int i = 0; i < 8; i++) {
                fma2(acc2[i][0], ad[i], b01.x);
                fma2(acc2[i][1], ad[i], b01.y);
                fma2(acc2[i][2], ad[i], b23.x);
                fma2(acc2[i][3], ad[i], b23.y);
            }
        }

        if (more) {
            const int nb = cb ^ 1;
            #pragma unroll
            for (int h = 0; h < 2; h++) {
                As[nb][ac0 + h * 4 + 0][arow] = pa[h].x;
                As[nb][ac0 + h * 4 + 1][arow] = pa[h].y;
                As[nb][ac0 + h * 4 + 2][arow] = pa[h].z;
                As[nb][ac0 + h * 4 + 3][arow] = pa[h].w;
                *(float4*)&Bs[nb][brow][bc0 + h * 4] = pb[h];
            }
            __syncthreads();
        }
    }

    #pragma unroll
    for (int i = 0; i < 8; i++) {
        int m = m0 + tm + i;
        #pragma unroll
        for (int j2 = 0; j2 < 4; j2++) {
            int n = n0 + tn + j2 * 2;
            if (n < N) {
                float2 v;
                v.x = lo2(acc2[i][j2]) + bias[n + 0];
                v.y = hi2(acc2[i][j2]) + bias[n + 1];
                *(float2*)(C + (size_t)m * N + n) = v;
            }
        }
    }
}

__global__ __launch_bounds__(256) void gemm_wqkvx(const float* __restrict__ input) {
    sgemm_body(input, g_W12, g_W12 + 512 * 400, g_wqkvx, TB, 400, 512, 512, 512);
}

__global__ __launch_bounds__(256) void gemm_dec(const float* __restrict__ dec_W,
                                                const float* __restrict__ dec_b,
                                                float* __restrict__ C) {
    sgemm_body(g_out, dec_W, dec_b, C, TB, NTOK, OSTRIDE, NHID, OSTRIDE);
}

// ---------------- persistent steps (R13 base; phase C gates rewritten) ------
struct StepSmem {
    float wh[25 * 300 * 4];    // smem-resident copy of g_Wh2 (120 KB)
    float hb[100][32];
    float hn[100][32];
    float hg[24][301];
    float wqk[4][100];
    float vx[4][300];
    float sarr[24], parr[24], bm[24];
    float q2[24][33], k2[24][33];
    float v2[24][101];
    float p2[24][8];
};

__global__ __launch_bounds__(640, 1) void steps_persistent(
    const float* __restrict__ hidden,
    const float* __restrict__ masks,
    const float* __restrict__ gru_b,
    float* __restrict__ hT_out,
    float* __restrict__ bmask_out)
{
    extern __shared__ __align__(16) char smem_raw[];
    StepSmem& s = *reinterpret_cast<StepSmem*>(smem_raw);

    const int tid = threadIdx.x;
    const int b0 = blockIdx.x * 4;

    {
        float4* dst = (float4*)s.wh;
        const float4* src = (const float4*)g_Wh2;
        for (int i = tid; i < 25 * 300; i += 640) dst[i] = src[i];
    }
    for (int i = tid; i < 2400; i += 640) {
        int bb = i / 600, j = i % 600;
        s.hb[j % 100][bb * 6 + j / 100] = hidden[(b0 + bb) * NHID + j];
    }
    for (int i = tid; i < T_ * 4 * (OSTRIDE - NHID); i += 640) {
        int t = i / (4 * (OSTRIDE - NHID));
        int r = i % (4 * (OSTRIDE - NHID));
        int bb = r / (OSTRIDE - NHID), c = r % (OSTRIDE - NHID);
        g_out[((size_t)t * B_ + b0 + bb) * OSTRIDE + NHID + c] = 0.f;
    }

    for (int t = 0; t < T_; t++) {
        __syncthreads();   // b1

        if (tid < 600) {
            const int col = (tid < 300) ? tid : tid - 300;
            const int g   = (tid < 300) ? 0 : 12;
            ull acc[6] = {0, 0, 0, 0, 0, 0};
            for (int kb = 0; kb < 25; kb++) {
                float4 wv = *(const float4*)&s.wh[(kb * 300 + col) * 4];
                const int k = kb * 4;
                #pragma unroll
                for (int kk = 0; kk < 4; kk++) {
                    float w = (kk == 0) ? wv.x : (kk == 1) ? wv.y : (kk == 2) ? wv.z : wv.w;
                    ull wd = dup2(w);
                    const ulonglong2* hr = (const ulonglong2*)&s.hb[k + kk][g];
                    ulonglong2 h01 = hr[0], h23 = hr[1], h45 = hr[2];
                    fma2(acc[0], h01.x, wd); fma2(acc[1], h01.y, wd);
                    fma2(acc[2], h23.x, wd); fma2(acc[3], h23.y, wd);
                    fma2(acc[4], h45.x, wd); fma2(acc[5], h45.y, wd);
                }
            }
            #pragma unroll
            for (int p = 0; p < 6; p++) {
                s.hg[g + 2 * p][col]     = lo2(acc[p]);
                s.hg[g + 2 * p + 1][col] = hi2(acc[p]);
            }
        } else if (tid >= 608) {
            const int lane = tid - 608;
            const float* src = g_wqkvx + (size_t)(t * B_ + b0) * 400;
            for (int j = lane; j < 100; j += 32) {
                int bb = j / 25, c4 = j % 25;
                *(float4*)&s.wqk[bb][c4 * 4] = *(const float4*)(src + bb * 400 + c4 * 4);
            }
            for (int j = lane; j < 300; j += 32) {
                int bb = j / 75, c4 = j % 75;
                *(float4*)&s.vx[bb][c4 * 4] = *(const float4*)(src + bb * 400 + 100 + c4 * 4);
            }
            __syncwarp();
            if (lane < 24) {
                const int u = lane, bb = u / 6;
                const float m = masks[t * B_ + b0 + bb];
                const float* w = s.wqk[bb];
                float sc = 0.f;
                #pragma unroll 4
                for (int k = 0; k < 100; k++) sc += s.hb[k][u] * w[k];
                sc *= 0.125f * m;
                s.sarr[u] = sc;
                s.parr[u] = 1.f / (1.f + expf(-sc));
            }
            __syncwarp();
            if (lane < 24) {
                const int u = lane, bb = u / 6, n = u % 6;
                float sn = s.sarr[u];
                int cnt = 0;
                #pragma unroll
                for (int m2 = 0; m2 < 6; m2++) {
                    float sm = s.sarr[bb * 6 + m2];
                    if (sm > sn || (sm == sn && m2 < n)) cnt++;
                }
                float v = (cnt < TOPK_) ? 1.f : 0.f;
                s.bm[u] = v;
                bmask_out[(size_t)t * B_ * NB + (b0 + bb) * NB + n] = v;
            }
        }
        __syncthreads();   // b2

        // ---- phase C: GRU gates -> hn  (MUFU-lean: shared reciprocal + exp-tanh)
        {
            const int u = tid & 31, jb = tid >> 5;
            if (u < 24) {
                const int bb = u / 6;
                const float m = masks[t * B_ + b0 + bb];
                const float p = s.parr[u];
                for (int j = jb; j < 100; j += 20) {
                    float xr = p * s.vx[bb][j]       + gru_b[j];
                    float xz = p * s.vx[bb][j + 100] + gru_b[j + 100];
                    float xn = p * s.vx[bb][j + 200] + gru_b[j + 200];
                    // sigmoid args (clamped to avoid inf in shared denominator)
                    float ar = xr + m * s.hg[u][j];
                    float az = xz + m * s.hg[u][j + 100];
                    ar = fminf(fmaxf(ar, -20.f), 20.f);
                    az = fminf(fmaxf(az, -20.f), 20.f);
                    float ea = __expf(-ar);
                    float eb = __expf(-az);
                    float da = 1.f + ea, db = 1.f + eb;
                    float inv = __fdividef(1.f, da * db);
                    float r_ = db * inv;              // sigmoid(ar)
                    float z_ = da * inv;              // sigmoid(az)
                    // tanh via exp (clamped)
                    float an = xn + r_ * (m * s.hg[u][j + 200]);
                    an = fminf(fmaxf(an, -15.f), 15.f);
                    float tt = __expf(-2.f * an);
                    float nn = __fdividef(1.f - tt, 1.f + tt);
                    s.hn[j][u] = (1.f - z_) * nn + z_ * (m * s.hb[j][u]);
                }
            }
        }
        __syncthreads();   // b3

        if (tid < 328) {
            const int col = (tid < 164) ? tid : tid - 164;
            const int g   = (tid < 164) ? 0 : 12;
            ull acc[6] = {0, 0, 0, 0, 0, 0};
            for (int kb = 0; kb < 25; kb++) {
                float4 wv = *(const float4*)&g_Wqkv2[(kb * 164 + col) * 4];
                const int k = kb * 4;
                #pragma unroll
                for (int kk = 0; kk < 4; kk++) {
                    float w = (kk == 0) ? wv.x : (kk == 1) ? wv.y : (kk == 2) ? wv.z : wv.w;
                    ull wd = dup2(w);
                    const ulonglong2* hr = (const ulonglong2*)&s.hn[k + kk][g];
                    ulonglong2 h01 = hr[0], h23 = hr[1], h45 = hr[2];
                    fma2(acc[0], h01.x, wd); fma2(acc[1], h01.y, wd);
                    fma2(acc[2], h23.x, wd); fma2(acc[3], h23.y, wd);
                    fma2(acc[4], h45.x, wd); fma2(acc[5], h45.y, wd);
                }
            }
            #pragma unroll
            for (int p = 0; p < 6; p++) {
                float x = lo2(acc[p]), y = hi2(acc[p]);
                int u0 = g + 2 * p, u1 = g + 2 * p + 1;
                if (col < 32)      { s.q2[u0][col] = x;      s.q2[u1][col] = y; }
                else if (col < 64) { s.k2[u0][col - 32] = x; s.k2[u1][col - 32] = y; }
                else               { s.v2[u0][col - 64] = x; s.v2[u1][col - 64] = y; }
            }
        }
        __syncthreads();   // b4

        if (tid < 128) {
            const int wd = tid >> 5, lane = tid & 31;
            const int bb = wd;
            for (int job = lane; job < 36; job += 32) {
                int n = job / 6, m2 = job % 6;
                const float* qr = s.q2[bb * 6 + n];
                const float* kr = s.k2[bb * 6 + m2];
                float sc = 0.f;
                #pragma unroll
                for (int d = 0; d < 32; d++) sc += qr[d] * kr[d];
                s.p2[bb * 6 + n][m2] = sc * 0.17677669529663687f;
            }
            __syncwarp();
            if (lane < 6) {
                const int u = bb * 6 + lane;
                float mx = -1e30f;
                #pragma unroll
                for (int m2 = 0; m2 < 6; m2++) mx = fmaxf(mx, s.p2[u][m2]);
                float e[6], sum = 0.f;
                #pragma unroll
                for (int m2 = 0; m2 < 6; m2++) { e[m2] = expf(s.p2[u][m2] - mx); sum += e[m2]; }
                float inv = 1.f / sum;
                #pragma unroll
                for (int m2 = 0; m2 < 6; m2++) s.p2[u][m2] = e[m2] * inv;
            }
        }
        __syncthreads();   // b5

        {
            const int u = tid & 31, jb = tid >> 5;
            if (u < 24) {
                const int bb = u / 6;
                const float m = masks[t * B_ + b0 + bb];
                const float bmu = s.bm[u];
                float pr[6];
                #pragma unroll
                for (int m2 = 0; m2 < 6; m2++) pr[m2] = s.p2[u][m2];
                for (int j = jb; j < 100; j += 20) {
                    float acc = s.hn[j][u];
                    #pragma unroll
                    for (int m2 = 0; m2 < 6; m2++) acc += pr[m2] * s.v2[bb * 6 + m2][j];
                    float res = (bmu > 0.5f) ? acc : (m * s.hb[j][u]);
                    s.hb[j][u] = res;
                    g_out[((size_t)t * B_ + b0 + bb) * OSTRIDE + (u % 6) * 100 + j] = res;
                }
            }
        }
    }

    __syncthreads();
    for (int i = tid; i < 2400; i += 640) {
        int bb = i / 600, j = i % 600;
        hT_out[(b0 + bb) * NHID + j] = s.hb[j % 100][bb * 6 + j / 100];
    }
}

// ---------------- launch ----------------
extern "C" void kernel_launch(void* const* d_in, const int* in_sizes, int n_in,
                              void* d_out, int out_size) {
    const float* input  = (const float*)d_in[0];
    const float* hidden = (const float*)d_in[1];
    const float* masks  = (const float*)d_in[2];
    const float* enc_W  = (const float*)d_in[3];
    const float* enc_b  = (const float*)d_in[4];
    const float* Wq     = (const float*)d_in[5];
    const float* Wk     = (const float*)d_in[6];
    const float* Wv     = (const float*)d_in[7];
    const float* Wx     = (const float*)d_in[8];
    const float* Wh     = (const float*)d_in[9];
    const float* gru_b  = (const float*)d_in[10];
    const float* Wq2    = (const float*)d_in[11];
    const float* Wk2    = (const float*)d_in[12];
    const float* Wv2    = (const float*)d_in[13];
    const float* dec_W  = (const float*)d_in[14];
    const float* dec_b  = (const float*)d_in[15];
    float* out = (float*)d_out;

    static int attr_set = 0;
    int step_smem = (int)sizeof(StepSmem);
    if (!attr_set) {
        cudaFuncSetAttribute(steps_persistent,
                             cudaFuncAttributeMaxDynamicSharedMemorySize, step_smem);
        attr_set = 1;
    }

    fold1<<<(513 * 404 + 255) / 256, 256>>>(enc_W, enc_b, Wk, Wv);
    fold2<<<(513 * 400 + 255) / 256, 256>>>(Wq, Wx);
    transposeW<<<(300 * 100 + 164 * 100 + 255) / 256, 256>>>(Wh, Wq2, Wk2, Wv2);

    gemm_wqkvx<<<dim3(4, TB / 128), 256>>>(input);

    float* hT_out    = out + DEC_OFF;
    float* bmask_out = out + DEC_OFF + B_ * NHID;
    steps_persistent<<<B_ / 4, 640, step_smem>>>(hidden, masks, gru_b, hT_out, bmask_out);

    gemm_dec<<<dim3(4, TB / 128), 256>>>(dec_W, dec_b, out);
}

// round 16
// speedup vs baseline: 1.3040x; 1.0149x over previous
#include <cuda_runtime.h>
#include <math.h>
#include <stdint.h>

#define T_    64
#define B_    512
#define NTOK  512
#define NINP  600
#define NHID  600
#define NB    6
#define TOPK_ 4
#define BS_   100
#define ATT   340
#define DK    64
#define DC    32

#define TB    (T_ * B_)              // 32768
#define DEC_OFF   (TB * NTOK)        // 16777216
#define OSTRIDE   608                // g_out row stride (16-multiple, 600 valid)

typedef unsigned long long ull;

// ---------------- f32x2 packed helpers ----------------
__device__ __forceinline__ ull dup2(float x) {
    ull r; asm("mov.b64 %0, {%1, %1};" : "=l"(r) : "f"(x)); return r;
}
__device__ __forceinline__ void fma2(ull &d, ull a, ull b) {
    asm("fma.rn.f32x2 %0, %1, %2, %0;" : "+l"(d) : "l"(a), "l"(b));
}
__device__ __forceinline__ float lo2(ull v) {
    float x, y; asm("mov.b64 {%0, %1}, %2;" : "=f"(x), "=f"(y) : "l"(v)); return x;
}
__device__ __forceinline__ float hi2(ull v) {
    float x, y; asm("mov.b64 {%0, %1}, %2;" : "=f"(x), "=f"(y) : "l"(v)); return y;
}

// ---------------- scratch (device globals) ----------------
__device__ float g_T1[513 * 404];
__device__ float g_W12[513 * 400];
__device__ float g_wqkvx[(size_t)TB * 400];
__device__ float g_out[(size_t)TB * OSTRIDE];
__device__ float g_Wh2[25 * 300 * 4];       // k-blocked: [(kb*300+c)*4 + kk] = Wh[kb*4+kk][c]
__device__ float g_Wqkv2[25 * 164 * 4];     // k-blocked: [(kb*164+c)*4 + kk]

// ---------------- fold kernels ----------------
__global__ void fold1(const float* __restrict__ enc_W, const float* __restrict__ enc_b,
                      const float* __restrict__ Wk,    const float* __restrict__ Wv) {
    int idx = blockIdx.x * blockDim.x + threadIdx.x;
    if (idx >= 513 * 404) return;
    int r = idx / 404, c = idx % 404;
    const float* arow = (r < 512) ? (enc_W + (size_t)r * NINP) : enc_b;
    float acc = 0.f;
    if (c < 64) {
        #pragma unroll 4
        for (int k = 0; k < NINP; k++) acc += arow[k] * __ldg(&Wk[k * DK + c]);
    } else {
        int cc = c - 64;
        #pragma unroll 4
        for (int k = 0; k < NINP; k++) acc += arow[k] * __ldg(&Wv[k * ATT + cc]);
    }
    g_T1[idx] = acc;
}

__global__ void fold2(const float* __restrict__ Wq, const float* __restrict__ Wx) {
    int idx = blockIdx.x * blockDim.x + threadIdx.x;
    if (idx >= 513 * 400) return;
    int r = idx / 400, c = idx % 400;
    float acc = 0.f;
    if (c < 100) {
        const float* t1 = g_T1 + r * 404;
        const float* wq = Wq + c * DK;
        #pragma unroll 8
        for (int k = 0; k < DK; k++) acc += t1[k] * wq[k];
    } else {
        const float* t1 = g_T1 + r * 404 + 64;
        int cc = c - 100;
        #pragma unroll 4
        for (int k = 0; k < ATT; k++) acc += t1[k] * __ldg(&Wx[k * 300 + cc]);
    }
    g_W12[idx] = acc;
}

// k-blocked step-weight layouts (coalesced warp loads: lanes = consecutive cols)
__global__ void transposeW(const float* __restrict__ Wh,
                           const float* __restrict__ Wq2,
                           const float* __restrict__ Wk2,
                           const float* __restrict__ Wv2) {
    int i = blockIdx.x * blockDim.x + threadIdx.x;
    if (i < 300 * 100) {
        int k = i / 300, c = i % 300;
        g_Wh2[(((k >> 2) * 300) + c) * 4 + (k & 3)] = Wh[k * 300 + c];
    } else if (i < 300 * 100 + 164 * 100) {
        int j = i - 300 * 100;
        int k = j / 164, c = j % 164;
        float v;
        if (c < 32)      v = Wq2[k * 32 + c];
        else if (c < 64) v = Wk2[k * 32 + (c - 32)];
        else             v = Wv2[k * 100 + (c - 64)];
        g_Wqkv2[(((k >> 2) * 164) + c) * 4 + (k & 3)] = v;
    }
}

// ---------------- fp32 SGEMM, BK=16 double-buffered (frozen layout) ---------
// Kt/Kvalid/Astride compile-time for better scheduling. Same body as R15.
template<int Kt, int Kvalid, int Astride>
__device__ __forceinline__ void sgemm_body(
    const float* __restrict__ A, const float* __restrict__ B,
    const float* __restrict__ bias, float* __restrict__ C, int N)
{
    __shared__ __align__(16) float As[2][16][128];
    __shared__ __align__(16) float Bs[2][16][128];
    const int tid = threadIdx.x;
    const int m0 = blockIdx.y * 128;
    const int n0 = blockIdx.x * 128;
    const int arow = tid >> 1, ac0 = (tid & 1) * 8;
    const int brow = tid >> 4, bc0 = (tid & 15) * 8;
    const int tm = (tid >> 4) * 8, tn = (tid & 15) * 8;
    constexpr int Kc = Kt / 16;

    ull acc2[8][4];
    #pragma unroll
    for (int i = 0; i < 8; i++)
        #pragma unroll
        for (int j = 0; j < 4; j++) acc2[i][j] = 0ull;

    {
        const float* ga = A + (size_t)(m0 + arow) * Astride + ac0;
        #pragma unroll
        for (int h = 0; h < 2; h++) {
            float4 av = *(const float4*)(ga + h * 4);
            As[0][ac0 + h * 4 + 0][arow] = av.x;
            As[0][ac0 + h * 4 + 1][arow] = av.y;
            As[0][ac0 + h * 4 + 2][arow] = av.z;
            As[0][ac0 + h * 4 + 3][arow] = av.w;
        }
        #pragma unroll
        for (int h = 0; h < 2; h++) {
            float4 bv = make_float4(0.f, 0.f, 0.f, 0.f);
            if (brow < Kvalid && n0 + bc0 + h * 4 < N)
                bv = *(const float4*)(B + (size_t)brow * N + n0 + bc0 + h * 4);
            *(float4*)&Bs[0][brow][bc0 + h * 4] = bv;
        }
    }
    __syncthreads();

    for (int kc = 0; kc < Kc; kc++) {
        float4 pa[2], pb[2];
        const bool more = (kc + 1 < Kc);
        if (more) {
            const int k1 = (kc + 1) * 16;
            const float* ga = A + (size_t)(m0 + arow) * Astride + k1 + ac0;
            #pragma unroll
            for (int h = 0; h < 2; h++) pa[h] = *(const float4*)(ga + h * 4);
            #pragma unroll
            for (int h = 0; h < 2; h++) {
                pb[h] = make_float4(0.f, 0.f, 0.f, 0.f);
                if (k1 + brow < Kvalid && n0 + bc0 + h * 4 < N)
                    pb[h] = *(const float4*)(B + (size_t)(k1 + brow) * N + n0 + bc0 + h * 4);
            }
        }

        const int cb = kc & 1;
        #pragma unroll
        for (int k = 0; k < 16; k++) {
            float4 a0 = *(const float4*)&As[cb][k][tm];
            float4 a1 = *(const float4*)&As[cb][k][tm + 4];
            ulonglong2 b01 = *(const ulonglong2*)&Bs[cb][k][tn];
            ulonglong2 b23 = *(const ulonglong2*)&Bs[cb][k][tn + 4];
            ull ad[8];
            ad[0] = dup2(a0.x); ad[1] = dup2(a0.y); ad[2] = dup2(a0.z); ad[3] = dup2(a0.w);
            ad[4] = dup2(a1.x); ad[5] = dup2(a1.y); ad[6] = dup2(a1.z); ad[7] = dup2(a1.w);
            #pragma unroll
            for (int i = 0; i < 8; i++) {
                fma2(acc2[i][0], ad[i], b01.x);
                fma2(acc2[i][1], ad[i], b01.y);
                fma2(acc2[i][2], ad[i], b23.x);
                fma2(acc2[i][3], ad[i], b23.y);
            }
        }

        if (more) {
            const int nb = cb ^ 1;
            #pragma unroll
            for (int h = 0; h < 2; h++) {
                As[nb][ac0 + h * 4 + 0][arow] = pa[h].x;
                As[nb][ac0 + h * 4 + 1][arow] = pa[h].y;
                As[nb][ac0 + h * 4 + 2][arow] = pa[h].z;
                As[nb][ac0 + h * 4 + 3][arow] = pa[h].w;
                *(float4*)&Bs[nb][brow][bc0 + h * 4] = pb[h];
            }
            __syncthreads();
        }
    }

    #pragma unroll
    for (int i = 0; i < 8; i++) {
        int m = m0 + tm + i;
        #pragma unroll
        for (int j2 = 0; j2 < 4; j2++) {
            int n = n0 + tn + j2 * 2;
            if (n < N) {
                float2 v;
                v.x = lo2(acc2[i][j2]) + bias[n + 0];
                v.y = hi2(acc2[i][j2]) + bias[n + 1];
                *(float2*)(C + (size_t)m * N + n) = v;
            }
        }
    }
}

__global__ __launch_bounds__(256) void gemm_wqkvx(const float* __restrict__ input) {
    sgemm_body<512, 512, 512>(input, g_W12, g_W12 + 512 * 400, g_wqkvx, 400);
}

__global__ __launch_bounds__(256) void gemm_dec(const float* __restrict__ dec_W,
                                                const float* __restrict__ dec_b,
                                                float* __restrict__ C) {
    sgemm_body<OSTRIDE, NHID, OSTRIDE>(g_out, dec_W, dec_b, C, NTOK);
}

// ---------------- persistent steps (R15 base; phase F staged + coalesced) ---
struct StepSmem {
    float wh[25 * 300 * 4];    // smem-resident copy of g_Wh2 (120 KB)
    float hb[100][32];
    float hn[100][32];
    float hg[24][301];         // phase-C input; reused as hc staging in phase F
    float wqk[4][100];
    float vx[4][300];
    float sarr[24], parr[24], bm[24];
    float q2[24][33], k2[24][33];
    float v2[24][101];
    float p2[24][8];
};

__global__ __launch_bounds__(640, 1) void steps_persistent(
    const float* __restrict__ hidden,
    const float* __restrict__ masks,
    const float* __restrict__ gru_b,
    float* __restrict__ hT_out,
    float* __restrict__ bmask_out)
{
    extern __shared__ __align__(16) char smem_raw[];
    StepSmem& s = *reinterpret_cast<StepSmem*>(smem_raw);

    const int tid = threadIdx.x;
    const int b0 = blockIdx.x * 4;

    {
        float4* dst = (float4*)s.wh;
        const float4* src = (const float4*)g_Wh2;
        for (int i = tid; i < 25 * 300; i += 640) dst[i] = src[i];
    }
    for (int i = tid; i < 2400; i += 640) {
        int bb = i / 600, j = i % 600;
        s.hb[j % 100][bb * 6 + j / 100] = hidden[(b0 + bb) * NHID + j];
    }
    for (int i = tid; i < T_ * 4 * (OSTRIDE - NHID); i += 640) {
        int t = i / (4 * (OSTRIDE - NHID));
        int r = i % (4 * (OSTRIDE - NHID));
        int bb = r / (OSTRIDE - NHID), c = r % (OSTRIDE - NHID);
        g_out[((size_t)t * B_ + b0 + bb) * OSTRIDE + NHID + c] = 0.f;
    }

    for (int t = 0; t < T_; t++) {
        __syncthreads();   // b1

        if (tid < 600) {
            const int col = (tid < 300) ? tid : tid - 300;
            const int g   = (tid < 300) ? 0 : 12;
            ull acc[6] = {0, 0, 0, 0, 0, 0};
            for (int kb = 0; kb < 25; kb++) {
                float4 wv = *(const float4*)&s.wh[(kb * 300 + col) * 4];
                const int k = kb * 4;
                #pragma unroll
                for (int kk = 0; kk < 4; kk++) {
                    float w = (kk == 0) ? wv.x : (kk == 1) ? wv.y : (kk == 2) ? wv.z : wv.w;
                    ull wd = dup2(w);
                    const ulonglong2* hr = (const ulonglong2*)&s.hb[k + kk][g];
                    ulonglong2 h01 = hr[0], h23 = hr[1], h45 = hr[2];
                    fma2(acc[0], h01.x, wd); fma2(acc[1], h01.y, wd);
                    fma2(acc[2], h23.x, wd); fma2(acc[3], h23.y, wd);
                    fma2(acc[4], h45.x, wd); fma2(acc[5], h45.y, wd);
                }
            }
            #pragma unroll
            for (int p = 0; p < 6; p++) {
                s.hg[g + 2 * p][col]     = lo2(acc[p]);
                s.hg[g + 2 * p + 1][col] = hi2(acc[p]);
            }
        } else if (tid >= 608) {
            const int lane = tid - 608;
            const float* src = g_wqkvx + (size_t)(t * B_ + b0) * 400;
            for (int j = lane; j < 100; j += 32) {
                int bb = j / 25, c4 = j % 25;
                *(float4*)&s.wqk[bb][c4 * 4] = *(const float4*)(src + bb * 400 + c4 * 4);
            }
            for (int j = lane; j < 300; j += 32) {
                int bb = j / 75, c4 = j % 75;
                *(float4*)&s.vx[bb][c4 * 4] = *(const float4*)(src + bb * 400 + 100 + c4 * 4);
            }
            __syncwarp();
            if (lane < 24) {
                const int u = lane, bb = u / 6;
                const float m = masks[t * B_ + b0 + bb];
                const float* w = s.wqk[bb];
                float sc = 0.f;
                #pragma unroll 4
                for (int k = 0; k < 100; k++) sc += s.hb[k][u] * w[k];
                sc *= 0.125f * m;
                s.sarr[u] = sc;
                s.parr[u] = 1.f / (1.f + expf(-sc));
            }
            __syncwarp();
            if (lane < 24) {
                const int u = lane, bb = u / 6, n = u % 6;
                float sn = s.sarr[u];
                int cnt = 0;
                #pragma unroll
                for (int m2 = 0; m2 < 6; m2++) {
                    float sm = s.sarr[bb * 6 + m2];
                    if (sm > sn || (sm == sn && m2 < n)) cnt++;
                }
                float v = (cnt < TOPK_) ? 1.f : 0.f;
                s.bm[u] = v;
                bmask_out[(size_t)t * B_ * NB + (b0 + bb) * NB + n] = v;
            }
        }
        __syncthreads();   // b2

        // ---- phase C: GRU gates -> hn  (MUFU-lean)
        {
            const int u = tid & 31, jb = tid >> 5;
            if (u < 24) {
                const int bb = u / 6;
                const float m = masks[t * B_ + b0 + bb];
                const float p = s.parr[u];
                for (int j = jb; j < 100; j += 20) {
                    float xr = p * s.vx[bb][j]       + gru_b[j];
                    float xz = p * s.vx[bb][j + 100] + gru_b[j + 100];
                    float xn = p * s.vx[bb][j + 200] + gru_b[j + 200];
                    float ar = xr + m * s.hg[u][j];
                    float az = xz + m * s.hg[u][j + 100];
                    ar = fminf(fmaxf(ar, -20.f), 20.f);
                    az = fminf(fmaxf(az, -20.f), 20.f);
                    float ea = __expf(-ar);
                    float eb = __expf(-az);
                    float da = 1.f + ea, db = 1.f + eb;
                    float inv = __fdividef(1.f, da * db);
                    float r_ = db * inv;
                    float z_ = da * inv;
                    float an = xn + r_ * (m * s.hg[u][j + 200]);
                    an = fminf(fmaxf(an, -15.f), 15.f);
                    float tt = __expf(-2.f * an);
                    float nn = __fdividef(1.f - tt, 1.f + tt);
                    s.hn[j][u] = (1.f - z_) * nn + z_ * (m * s.hb[j][u]);
                }
            }
        }
        __syncthreads();   // b3

        if (tid < 328) {
            const int col = (tid < 164) ? tid : tid - 164;
            const int g   = (tid < 164) ? 0 : 12;
            ull acc[6] = {0, 0, 0, 0, 0, 0};
            for (int kb = 0; kb < 25; kb++) {
                float4 wv = *(const float4*)&g_Wqkv2[(kb * 164 + col) * 4];
                const int k = kb * 4;
                #pragma unroll
                for (int kk = 0; kk < 4; kk++) {
                    float w = (kk == 0) ? wv.x : (kk == 1) ? wv.y : (kk == 2) ? wv.z : wv.w;
                    ull wd = dup2(w);
                    const ulonglong2* hr = (const ulonglong2*)&s.hn[k + kk][g];
                    ulonglong2 h01 = hr[0], h23 = hr[1], h45 = hr[2];
                    fma2(acc[0], h01.x, wd); fma2(acc[1], h01.y, wd);
                    fma2(acc[2], h23.x, wd); fma2(acc[3], h23.y, wd);
                    fma2(acc[4], h45.x, wd); fma2(acc[5], h45.y, wd);
                }
            }
            #pragma unroll
            for (int p = 0; p < 6; p++) {
                float x = lo2(acc[p]), y = hi2(acc[p]);
                int u0 = g + 2 * p, u1 = g + 2 * p + 1;
                if (col < 32)      { s.q2[u0][col] = x;      s.q2[u1][col] = y; }
                else if (col < 64) { s.k2[u0][col - 32] = x; s.k2[u1][col - 32] = y; }
                else               { s.v2[u0][col - 64] = x; s.v2[u1][col - 64] = y; }
            }
        }
        __syncthreads();   // b4

        if (tid < 128) {
            const int wd = tid >> 5, lane = tid & 31;
            const int bb = wd;
            for (int job = lane; job < 36; job += 32) {
                int n = job / 6, m2 = job % 6;
                const float* qr = s.q2[bb * 6 + n];
                const float* kr = s.k2[bb * 6 + m2];
                float sc = 0.f;
                #pragma unroll
                for (int d = 0; d < 32; d++) sc += qr[d] * kr[d];
                s.p2[bb * 6 + n][m2] = sc * 0.17677669529663687f;
            }
            __syncwarp();
            if (lane < 6) {
                const int u = bb * 6 + lane;
                float mx = -1e30f;
                #pragma unroll
                for (int m2 = 0; m2 < 6; m2++) mx = fmaxf(mx, s.p2[u][m2]);
                float e[6], sum = 0.f;
                #pragma unroll
                for (int m2 = 0; m2 < 6; m2++) { e[m2] = expf(s.p2[u][m2] - mx); sum += e[m2]; }
                float inv = 1.f / sum;
                #pragma unroll
                for (int m2 = 0; m2 < 6; m2++) s.p2[u][m2] = e[m2] * inv;
            }
        }
        __syncthreads();   // b5

        // ---- phase F: hc = hn + p2@v2; blend; update state; stage into hg
        {
            const int u = tid & 31, jb = tid >> 5;
            if (u < 24) {
                const int bb = u / 6;
                const float m = masks[t * B_ + b0 + bb];
                const float bmu = s.bm[u];
                float pr[6];
                #pragma unroll
                for (int m2 = 0; m2 < 6; m2++) pr[m2] = s.p2[u][m2];
                for (int j = jb; j < 100; j += 20) {
                    float acc = s.hn[j][u];
                    #pragma unroll
                    for (int m2 = 0; m2 < 6; m2++) acc += pr[m2] * s.v2[bb * 6 + m2][j];
                    float res = (bmu > 0.5f) ? acc : (m * s.hb[j][u]);
                    s.hb[j][u] = res;
                    s.hg[u][j] = res;          // stage (hg dead after phase C)
                }
            }
        }
        __syncthreads();   // b6: staged hc complete

        // ---- writer: coalesced history store (consecutive tid -> consecutive addr)
        {
            float* dst = g_out + (size_t)(t * B_ + b0) * OSTRIDE;
            for (int i = tid; i < 2400; i += 640) {
                int bb = i / 600, r = i % 600;
                dst[bb * OSTRIDE + r] = s.hg[bb * 6 + r / 100][r % 100];
            }
        }
    }

    __syncthreads();
    for (int i = tid; i < 2400; i += 640) {
        int bb = i / 600, j = i % 600;
        hT_out[(b0 + bb) * NHID + j] = s.hb[j % 100][bb * 6 + j / 100];
    }
}

// ---------------- launch ----------------
extern "C" void kernel_launch(void* const* d_in, const int* in_sizes, int n_in,
                              void* d_out, int out_size) {
    const float* input  = (const float*)d_in[0];
    const float* hidden = (const float*)d_in[1];
    const float* masks  = (const float*)d_in[2];
    const float* enc_W  = (const float*)d_in[3];
    const float* enc_b  = (const float*)d_in[4];
    const float* Wq     = (const float*)d_in[5];
    const float* Wk     = (const float*)d_in[6];
    const float* Wv     = (const float*)d_in[7];
    const float* Wx     = (const float*)d_in[8];
    const float* Wh     = (const float*)d_in[9];
    const float* gru_b  = (const float*)d_in[10];
    const float* Wq2    = (const float*)d_in[11];
    const float* Wk2    = (const float*)d_in[12];
    const float* Wv2    = (const float*)d_in[13];
    const float* dec_W  = (const float*)d_in[14];
    const float* dec_b  = (const float*)d_in[15];
    float* out = (float*)d_out;

    static int attr_set = 0;
    int step_smem = (int)sizeof(StepSmem);
    if (!attr_set) {
        cudaFuncSetAttribute(steps_persistent,
                             cudaFuncAttributeMaxDynamicSharedMemorySize, step_smem);
        attr_set = 1;
    }

    fold1<<<(513 * 404 + 255) / 256, 256>>>(enc_W, enc_b, Wk, Wv);
    fold2<<<(513 * 400 + 255) / 256, 256>>>(Wq, Wx);
    transposeW<<<(300 * 100 + 164 * 100 + 255) / 256, 256>>>(Wh, Wq2, Wk2, Wv2);

    gemm_wqkvx<<<dim3(4, TB / 128), 256>>>(input);

    float* hT_out    = out + DEC_OFF;
    float* bmask_out = out + DEC_OFF + B_ * NHID;
    steps_persistent<<<B_ / 4, 640, step_smem>>>(hidden, masks, gru_b, hT_out, bmask_out);

    gemm_dec<<<dim3(4, TB / 128), 256>>>(dec_W, dec_b, out);
}

// round 17
// speedup vs baseline: 1.3677x; 1.0489x over previous
#include <cuda_runtime.h>
#include <math.h>
#include <stdint.h>

#define T_    64
#define B_    512
#define NTOK  512
#define NINP  600
#define NHID  600
#define NB    6
#define TOPK_ 4
#define BS_   100
#define ATT   340
#define DK    64
#define DC    32

#define TB    (T_ * B_)              // 32768
#define DEC_OFF   (TB * NTOK)        // 16777216
#define OSTRIDE   608                // g_out row stride (16-multiple, 600 valid)

typedef unsigned long long ull;

// ---------------- f32x2 packed helpers ----------------
__device__ __forceinline__ ull dup2(float x) {
    ull r; asm("mov.b64 %0, {%1, %1};" : "=l"(r) : "f"(x)); return r;
}
__device__ __forceinline__ void fma2(ull &d, ull a, ull b) {
    asm("fma.rn.f32x2 %0, %1, %2, %0;" : "+l"(d) : "l"(a), "l"(b));
}
__device__ __forceinline__ float lo2(ull v) {
    float x, y; asm("mov.b64 {%0, %1}, %2;" : "=f"(x), "=f"(y) : "l"(v)); return x;
}
__device__ __forceinline__ float hi2(ull v) {
    float x, y; asm("mov.b64 {%0, %1}, %2;" : "=f"(x), "=f"(y) : "l"(v)); return y;
}

// ---------------- scratch (device globals) ----------------
__device__ float g_T1[513 * 404];
__device__ float g_W12[513 * 400];
__device__ float g_wqkvx[(size_t)TB * 400];
__device__ float g_out[(size_t)TB * OSTRIDE];
__device__ float g_Wh2[25 * 300 * 4];       // k-blocked: [(kb*300+c)*4 + kk] = Wh[kb*4+kk][c]
__device__ float g_Wqkv2[25 * 164 * 4];     // k-blocked: [(kb*164+c)*4 + kk]

// ---------------- fold kernels ----------------
__global__ void fold1(const float* __restrict__ enc_W, const float* __restrict__ enc_b,
                      const float* __restrict__ Wk,    const float* __restrict__ Wv) {
    int idx = blockIdx.x * blockDim.x + threadIdx.x;
    if (idx >= 513 * 404) return;
    int r = idx / 404, c = idx % 404;
    const float* arow = (r < 512) ? (enc_W + (size_t)r * NINP) : enc_b;
    float acc = 0.f;
    if (c < 64) {
        #pragma unroll 4
        for (int k = 0; k < NINP; k++) acc += arow[k] * __ldg(&Wk[k * DK + c]);
    } else {
        int cc = c - 64;
        #pragma unroll 4
        for (int k = 0; k < NINP; k++) acc += arow[k] * __ldg(&Wv[k * ATT + cc]);
    }
    g_T1[idx] = acc;
}

__global__ void fold2(const float* __restrict__ Wq, const float* __restrict__ Wx) {
    int idx = blockIdx.x * blockDim.x + threadIdx.x;
    if (idx >= 513 * 400) return;
    int r = idx / 400, c = idx % 400;
    float acc = 0.f;
    if (c < 100) {
        const float* t1 = g_T1 + r * 404;
        const float* wq = Wq + c * DK;
        #pragma unroll 8
        for (int k = 0; k < DK; k++) acc += t1[k] * wq[k];
    } else {
        const float* t1 = g_T1 + r * 404 + 64;
        int cc = c - 100;
        #pragma unroll 4
        for (int k = 0; k < ATT; k++) acc += t1[k] * __ldg(&Wx[k * 300 + cc]);
    }
    g_W12[idx] = acc;
}

// k-blocked step-weight layouts (coalesced warp loads: lanes = consecutive cols)
__global__ void transposeW(const float* __restrict__ Wh,
                           const float* __restrict__ Wq2,
                           const float* __restrict__ Wk2,
                           const float* __restrict__ Wv2) {
    int i = blockIdx.x * blockDim.x + threadIdx.x;
    if (i < 300 * 100) {
        int k = i / 300, c = i % 300;
        g_Wh2[(((k >> 2) * 300) + c) * 4 + (k & 3)] = Wh[k * 300 + c];
    } else if (i < 300 * 100 + 164 * 100) {
        int j = i - 300 * 100;
        int k = j / 164, c = j % 164;
        float v;
        if (c < 32)      v = Wq2[k * 32 + c];
        else if (c < 64) v = Wk2[k * 32 + (c - 32)];
        else             v = Wv2[k * 100 + (c - 64)];
        g_Wqkv2[(((k >> 2) * 164) + c) * 4 + (k & 3)] = v;
    }
}

// ---------------- fp32 SGEMM, BK=16 double-buffered + Bs bank-deswizzle -----
// Granule swizzle: 16B granule g in [0,32) stored at g ^ (g>>3). Makes both the
// loader STS.128 and the inner-loop LDS.128 conflict-free per quarter-warp.
template<int Kt, int Kvalid, int Astride>
__device__ __forceinline__ void sgemm_body(
    const float* __restrict__ A, const float* __restrict__ B,
    const float* __restrict__ bias, float* __restrict__ C, int N)
{
    __shared__ __align__(16) float As[2][16][128];
    __shared__ __align__(16) float Bs[2][16][128];
    const int tid = threadIdx.x;
    const int m0 = blockIdx.y * 128;
    const int n0 = blockIdx.x * 128;
    const int arow = tid >> 1, ac0 = (tid & 1) * 8;
    const int brow = tid >> 4, bc0 = (tid & 15) * 8;
    const int tm = (tid >> 4) * 8, tn = (tid & 15) * 8;
    constexpr int Kc = Kt / 16;

    // swizzled float-offsets for this thread's B granules
    const int lg0 = (tid & 15) * 2;                    // logical granule (= tn>>2 = bc0>>2)
    const int swr0 = (lg0 ^ (lg0 >> 3)) * 4;           // read granule 0
    const int swr1 = ((lg0 + 1) ^ ((lg0 + 1) >> 3)) * 4; // read granule 1
    const int sww0 = swr0;                             // write granules (same pattern)
    const int sww1 = swr1;

    ull acc2[8][4];
    #pragma unroll
    for (int i = 0; i < 8; i++)
        #pragma unroll
        for (int j = 0; j < 4; j++) acc2[i][j] = 0ull;

    {
        const float* ga = A + (size_t)(m0 + arow) * Astride + ac0;
        #pragma unroll
        for (int h = 0; h < 2; h++) {
            float4 av = *(const float4*)(ga + h * 4);
            As[0][ac0 + h * 4 + 0][arow] = av.x;
            As[0][ac0 + h * 4 + 1][arow] = av.y;
            As[0][ac0 + h * 4 + 2][arow] = av.z;
            As[0][ac0 + h * 4 + 3][arow] = av.w;
        }
        #pragma unroll
        for (int h = 0; h < 2; h++) {
            float4 bv = make_float4(0.f, 0.f, 0.f, 0.f);
            if (brow < Kvalid && n0 + bc0 + h * 4 < N)
                bv = *(const float4*)(B + (size_t)brow * N + n0 + bc0 + h * 4);
            *(float4*)&Bs[0][brow][h == 0 ? sww0 : sww1] = bv;
        }
    }
    __syncthreads();

    for (int kc = 0; kc < Kc; kc++) {
        float4 pa[2], pb[2];
        const bool more = (kc + 1 < Kc);
        if (more) {
            const int k1 = (kc + 1) * 16;
            const float* ga = A + (size_t)(m0 + arow) * Astride + k1 + ac0;
            #pragma unroll
            for (int h = 0; h < 2; h++) pa[h] = *(const float4*)(ga + h * 4);
            #pragma unroll
            for (int h = 0; h < 2; h++) {
                pb[h] = make_float4(0.f, 0.f, 0.f, 0.f);
                if (k1 + brow < Kvalid && n0 + bc0 + h * 4 < N)
                    pb[h] = *(const float4*)(B + (size_t)(k1 + brow) * N + n0 + bc0 + h * 4);
            }
        }

        const int cb = kc & 1;
        #pragma unroll
        for (int k = 0; k < 16; k++) {
            float4 a0 = *(const float4*)&As[cb][k][tm];
            float4 a1 = *(const float4*)&As[cb][k][tm + 4];
            ulonglong2 b01 = *(const ulonglong2*)&Bs[cb][k][swr0];
            ulonglong2 b23 = *(const ulonglong2*)&Bs[cb][k][swr1];
            ull ad[8];
            ad[0] = dup2(a0.x); ad[1] = dup2(a0.y); ad[2] = dup2(a0.z); ad[3] = dup2(a0.w);
            ad[4] = dup2(a1.x); ad[5] = dup2(a1.y); ad[6] = dup2(a1.z); ad[7] = dup2(a1.w);
            #pragma unroll
            for (int i = 0; i < 8; i++) {
                fma2(acc2[i][0], ad[i], b01.x);
                fma2(acc2[i][1], ad[i], b01.y);
                fma2(acc2[i][2], ad[i], b23.x);
                fma2(acc2[i][3], ad[i], b23.y);
            }
        }

        if (more) {
            const int nb = cb ^ 1;
            #pragma unroll
            for (int h = 0; h < 2; h++) {
                As[nb][ac0 + h * 4 + 0][arow] = pa[h].x;
                As[nb][ac0 + h * 4 + 1][arow] = pa[h].y;
                As[nb][ac0 + h * 4 + 2][arow] = pa[h].z;
                As[nb][ac0 + h * 4 + 3][arow] = pa[h].w;
                *(float4*)&Bs[nb][brow][h == 0 ? sww0 : sww1] = pb[h];
            }
            __syncthreads();
        }
    }

    #pragma unroll
    for (int i = 0; i < 8; i++) {
        int m = m0 + tm + i;
        #pragma unroll
        for (int j2 = 0; j2 < 4; j2++) {
            int n = n0 + tn + j2 * 2;
            if (n < N) {
                float2 v;
                v.x = lo2(acc2[i][j2]) + bias[n + 0];
                v.y = hi2(acc2[i][j2]) + bias[n + 1];
                *(float2*)(C + (size_t)m * N + n) = v;
            }
        }
    }
}

__global__ __launch_bounds__(256) void gemm_wqkvx(const float* __restrict__ input) {
    sgemm_body<512, 512, 512>(input, g_W12, g_W12 + 512 * 400, g_wqkvx, 400);
}

__global__ __launch_bounds__(256) void gemm_dec(const float* __restrict__ dec_W,
                                                const float* __restrict__ dec_b,
                                                float* __restrict__ C) {
    sgemm_body<OSTRIDE, NHID, OSTRIDE>(g_out, dec_W, dec_b, C, NTOK);
}

// ---------------- persistent steps (R16, proven) ----------------------------
struct StepSmem {
    float wh[25 * 300 * 4];    // smem-resident copy of g_Wh2 (120 KB)
    float hb[100][32];
    float hn[100][32];
    float hg[24][301];         // phase-C input; reused as hc staging in phase F
    float wqk[4][100];
    float vx[4][300];
    float sarr[24], parr[24], bm[24];
    float q2[24][33], k2[24][33];
    float v2[24][101];
    float p2[24][8];
};

__global__ __launch_bounds__(640, 1) void steps_persistent(
    const float* __restrict__ hidden,
    const float* __restrict__ masks,
    const float* __restrict__ gru_b,
    float* __restrict__ hT_out,
    float* __restrict__ bmask_out)
{
    extern __shared__ __align__(16) char smem_raw[];
    StepSmem& s = *reinterpret_cast<StepSmem*>(smem_raw);

    const int tid = threadIdx.x;
    const int b0 = blockIdx.x * 4;

    {
        float4* dst = (float4*)s.wh;
        const float4* src = (const float4*)g_Wh2;
        for (int i = tid; i < 25 * 300; i += 640) dst[i] = src[i];
    }
    for (int i = tid; i < 2400; i += 640) {
        int bb = i / 600, j = i % 600;
        s.hb[j % 100][bb * 6 + j / 100] = hidden[(b0 + bb) * NHID + j];
    }
    for (int i = tid; i < T_ * 4 * (OSTRIDE - NHID); i += 640) {
        int t = i / (4 * (OSTRIDE - NHID));
        int r = i % (4 * (OSTRIDE - NHID));
        int bb = r / (OSTRIDE - NHID), c = r % (OSTRIDE - NHID);
        g_out[((size_t)t * B_ + b0 + bb) * OSTRIDE + NHID + c] = 0.f;
    }

    for (int t = 0; t < T_; t++) {
        __syncthreads();   // b1

        if (tid < 600) {
            const int col = (tid < 300) ? tid : tid - 300;
            const int g   = (tid < 300) ? 0 : 12;
            ull acc[6] = {0, 0, 0, 0, 0, 0};
            for (int kb = 0; kb < 25; kb++) {
                float4 wv = *(const float4*)&s.wh[(kb * 300 + col) * 4];
                const int k = kb * 4;
                #pragma unroll
                for (int kk = 0; kk < 4; kk++) {
                    float w = (kk == 0) ? wv.x : (kk == 1) ? wv.y : (kk == 2) ? wv.z : wv.w;
                    ull wd = dup2(w);
                    const ulonglong2* hr = (const ulonglong2*)&s.hb[k + kk][g];
                    ulonglong2 h01 = hr[0], h23 = hr[1], h45 = hr[2];
                    fma2(acc[0], h01.x, wd); fma2(acc[1], h01.y, wd);
                    fma2(acc[2], h23.x, wd); fma2(acc[3], h23.y, wd);
                    fma2(acc[4], h45.x, wd); fma2(acc[5], h45.y, wd);
                }
            }
            #pragma unroll
            for (int p = 0; p < 6; p++) {
                s.hg[g + 2 * p][col]     = lo2(acc[p]);
                s.hg[g + 2 * p + 1][col] = hi2(acc[p]);
            }
        } else if (tid >= 608) {
            const int lane = tid - 608;
            const float* src = g_wqkvx + (size_t)(t * B_ + b0) * 400;
            for (int j = lane; j < 100; j += 32) {
                int bb = j / 25, c4 = j % 25;
                *(float4*)&s.wqk[bb][c4 * 4] = *(const float4*)(src + bb * 400 + c4 * 4);
            }
            for (int j = lane; j < 300; j += 32) {
                int bb = j / 75, c4 = j % 75;
                *(float4*)&s.vx[bb][c4 * 4] = *(const float4*)(src + bb * 400 + 100 + c4 * 4);
            }
            __syncwarp();
            if (lane < 24) {
                const int u = lane, bb = u / 6;
                const float m = masks[t * B_ + b0 + bb];
                const float* w = s.wqk[bb];
                float sc = 0.f;
                #pragma unroll 4
                for (int k = 0; k < 100; k++) sc += s.hb[k][u] * w[k];
                sc *= 0.125f * m;
                s.sarr[u] = sc;
                s.parr[u] = 1.f / (1.f + expf(-sc));
            }
            __syncwarp();
            if (lane < 24) {
                const int u = lane, bb = u / 6, n = u % 6;
                float sn = s.sarr[u];
                int cnt = 0;
                #pragma unroll
                for (int m2 = 0; m2 < 6; m2++) {
                    float sm = s.sarr[bb * 6 + m2];
                    if (sm > sn || (sm == sn && m2 < n)) cnt++;
                }
                float v = (cnt < TOPK_) ? 1.f : 0.f;
                s.bm[u] = v;
                bmask_out[(size_t)t * B_ * NB + (b0 + bb) * NB + n] = v;
            }
        }
        __syncthreads();   // b2

        // ---- phase C: GRU gates -> hn  (MUFU-lean)
        {
            const int u = tid & 31, jb = tid >> 5;
            if (u < 24) {
                const int bb = u / 6;
                const float m = masks[t * B_ + b0 + bb];
                const float p = s.parr[u];
                for (int j = jb; j < 100; j += 20) {
                    float xr = p * s.vx[bb][j]       + gru_b[j];
                    float xz = p * s.vx[bb][j + 100] + gru_b[j + 100];
                    float xn = p * s.vx[bb][j + 200] + gru_b[j + 200];
                    float ar = xr + m * s.hg[u][j];
                    float az = xz + m * s.hg[u][j + 100];
                    ar = fminf(fmaxf(ar, -20.f), 20.f);
                    az = fminf(fmaxf(az, -20.f), 20.f);
                    float ea = __expf(-ar);
                    float eb = __expf(-az);
                    float da = 1.f + ea, db = 1.f + eb;
                    float inv = __fdividef(1.f, da * db);
                    float r_ = db * inv;
                    float z_ = da * inv;
                    float an = xn + r_ * (m * s.hg[u][j + 200]);
                    an = fminf(fmaxf(an, -15.f), 15.f);
                    float tt = __expf(-2.f * an);
                    float nn = __fdividef(1.f - tt, 1.f + tt);
                    s.hn[j][u] = (1.f - z_) * nn + z_ * (m * s.hb[j][u]);
                }
            }
        }
        __syncthreads();   // b3

        if (tid < 328) {
            const int col = (tid < 164) ? tid : tid - 164;
            const int g   = (tid < 164) ? 0 : 12;
            ull acc[6] = {0, 0, 0, 0, 0, 0};
            for (int kb = 0; kb < 25; kb++) {
                float4 wv = *(const float4*)&g_Wqkv2[(kb * 164 + col) * 4];
                const int k = kb * 4;
                #pragma unroll
                for (int kk = 0; kk < 4; kk++) {
                    float w = (kk == 0) ? wv.x : (kk == 1) ? wv.y : (kk == 2) ? wv.z : wv.w;
                    ull wd = dup2(w);
                    const ulonglong2* hr = (const ulonglong2*)&s.hn[k + kk][g];
                    ulonglong2 h01 = hr[0], h23 = hr[1], h45 = hr[2];
                    fma2(acc[0], h01.x, wd); fma2(acc[1], h01.y, wd);
                    fma2(acc[2], h23.x, wd); fma2(acc[3], h23.y, wd);
                    fma2(acc[4], h45.x, wd); fma2(acc[5], h45.y, wd);
                }
            }
            #pragma unroll
            for (int p = 0; p < 6; p++) {
                float x = lo2(acc[p]), y = hi2(acc[p]);
                int u0 = g + 2 * p, u1 = g + 2 * p + 1;
                if (col < 32)      { s.q2[u0][col] = x;      s.q2[u1][col] = y; }
                else if (col < 64) { s.k2[u0][col - 32] = x; s.k2[u1][col - 32] = y; }
                else               { s.v2[u0][col - 64] = x; s.v2[u1][col - 64] = y; }
            }
        }
        __syncthreads();   // b4

        if (tid < 128) {
            const int wd = tid >> 5, lane = tid & 31;
            const int bb = wd;
            for (int job = lane; job < 36; job += 32) {
                int n = job / 6, m2 = job % 6;
                const float* qr = s.q2[bb * 6 + n];
                const float* kr = s.k2[bb * 6 + m2];
                float sc = 0.f;
                #pragma unroll
                for (int d = 0; d < 32; d++) sc += qr[d] * kr[d];
                s.p2[bb * 6 + n][m2] = sc * 0.17677669529663687f;
            }
            __syncwarp();
            if (lane < 6) {
                const int u = bb * 6 + lane;
                float mx = -1e30f;
                #pragma unroll
                for (int m2 = 0; m2 < 6; m2++) mx = fmaxf(mx, s.p2[u][m2]);
                float e[6], sum = 0.f;
                #pragma unroll
                for (int m2 = 0; m2 < 6; m2++) { e[m2] = expf(s.p2[u][m2] - mx); sum += e[m2]; }
                float inv = 1.f / sum;
                #pragma unroll
                for (int m2 = 0; m2 < 6; m2++) s.p2[u][m2] = e[m2] * inv;
            }
        }
        __syncthreads();   // b5

        // ---- phase F: hc = hn + p2@v2; blend; update state; stage into hg
        {
            const int u = tid & 31, jb = tid >> 5;
            if (u < 24) {
                const int bb = u / 6;
                const float m = masks[t * B_ + b0 + bb];
                const float bmu = s.bm[u];
                float pr[6];
                #pragma unroll
                for (int m2 = 0; m2 < 6; m2++) pr[m2] = s.p2[u][m2];
                for (int j = jb; j < 100; j += 20) {
                    float acc = s.hn[j][u];
                    #pragma unroll
                    for (int m2 = 0; m2 < 6; m2++) acc += pr[m2] * s.v2[bb * 6 + m2][j];
                    float res = (bmu > 0.5f) ? acc : (m * s.hb[j][u]);
                    s.hb[j][u] = res;
                    s.hg[u][j] = res;          // stage (hg dead after phase C)
                }
            }
        }
        __syncthreads();   // b6: staged hc complete

        // ---- writer: coalesced history store
        {
            float* dst = g_out + (size_t)(t * B_ + b0) * OSTRIDE;
            for (int i = tid; i < 2400; i += 640) {
                int bb = i / 600, r = i % 600;
                dst[bb * OSTRIDE + r] = s.hg[bb * 6 + r / 100][r % 100];
            }
        }
    }

    __syncthreads();
    for (int i = tid; i < 2400; i += 640) {
        int bb = i / 600, j = i % 600;
        hT_out[(b0 + bb) * NHID + j] = s.hb[j % 100][bb * 6 + j / 100];
    }
}

// ---------------- launch ----------------
extern "C" void kernel_launch(void* const* d_in, const int* in_sizes, int n_in,
                              void* d_out, int out_size) {
    const float* input  = (const float*)d_in[0];
    const float* hidden = (const float*)d_in[1];
    const float* masks  = (const float*)d_in[2];
    const float* enc_W  = (const float*)d_in[3];
    const float* enc_b  = (const float*)d_in[4];
    const float* Wq     = (const float*)d_in[5];
    const float* Wk     = (const float*)d_in[6];
    const float* Wv     = (const float*)d_in[7];
    const float* Wx     = (const float*)d_in[8];
    const float* Wh     = (const float*)d_in[9];
    const float* gru_b  = (const float*)d_in[10];
    const float* Wq2    = (const float*)d_in[11];
    const float* Wk2    = (const float*)d_in[12];
    const float* Wv2    = (const float*)d_in[13];
    const float* dec_W  = (const float*)d_in[14];
    const float* dec_b  = (const float*)d_in[15];
    float* out = (float*)d_out;

    static int attr_set = 0;
    int step_smem = (int)sizeof(StepSmem);
    if (!attr_set) {
        cudaFuncSetAttribute(steps_persistent,
                             cudaFuncAttributeMaxDynamicSharedMemorySize, step_smem);
        attr_set = 1;
    }

    fold1<<<(513 * 404 + 255) / 256, 256>>>(enc_W, enc_b, Wk, Wv);
    fold2<<<(513 * 400 + 255) / 256, 256>>>(Wq, Wx);
    transposeW<<<(300 * 100 + 164 * 100 + 255) / 256, 256>>>(Wh, Wq2, Wk2, Wv2);

    gemm_wqkvx<<<dim3(4, TB / 128), 256>>>(input);

    float* hT_out    = out + DEC_OFF;
    float* bmask_out = out + DEC_OFF + B_ * NHID;
    steps_persistent<<<B_ / 4, 640, step_smem>>>(hidden, masks, gru_b, hT_out, bmask_out);

    gemm_dec<<<dim3(4, TB / 128), 256>>>(dec_W, dec_b, out);
}